// round 1
// baseline (speedup 1.0000x reference)
#include <cuda_runtime.h>
#include <math.h>

#define NTOK (8 * 2048)      // 16384 rows
#define DIM  1024
#define MSL  64              // memory slots
#define KTOP 3
#define LN_EPS 1e-5f

// Scratch (allocation-free rule: __device__ globals)
__device__ float g_Q[(size_t)NTOK * DIM];        // query projection
__device__ float g_MO[(size_t)NTOK * DIM];       // memory_output
__device__ float g_H[(size_t)NTOK * DIM];        // fusion pre-LN

// ---------------------------------------------------------------------------
// Tiled SGEMM: C[n,e] = sum_k A(n,k) * B[e,k] + bias[e]
// A is virtually [NTOK, K]: first DIM cols from A0, next DIM from A1 (if K>DIM).
// B is [1024, K] row-major (K contiguous). C is [NTOK, 1024].
// BM=BN=128, BK=16, 256 threads, 8x8 per thread.
// ---------------------------------------------------------------------------
#define BM 128
#define BN 128
#define BKK 16
#define TM 8
#define TN 8

__global__ void __launch_bounds__(256) sgemm_kernel(
    const float* __restrict__ A0,
    const float* __restrict__ A1,       // may be null (K == DIM)
    const float* __restrict__ B,        // [1024, K]
    const float* __restrict__ bias,     // [1024]
    float* __restrict__ C,              // [NTOK, 1024]
    int K)
{
    __shared__ float As[BKK][BM + 4];
    __shared__ float Bs[BKK][BN + 4];

    const int n0 = blockIdx.y * BM;
    const int e0 = blockIdx.x * BN;
    const int tid = threadIdx.x;
    const int ty = tid >> 4;          // 0..15
    const int tx = tid & 15;          // 0..15

    float acc[TM][TN];
#pragma unroll
    for (int i = 0; i < TM; i++)
#pragma unroll
        for (int j = 0; j < TN; j++) acc[i][j] = 0.f;

    for (int kt = 0; kt < K; kt += BKK) {
        const float* Asrc = A0;
        int kk0 = kt;
        if (A1 != nullptr && kt >= DIM) { Asrc = A1; kk0 = kt - DIM; }

        // Load A tile: 128 rows x 16 cols = 512 float4, 2 per thread
#pragma unroll
        for (int i = 0; i < 2; i++) {
            int f = tid + i * 256;
            int r = f >> 2;
            int c4 = (f & 3) * 4;
            float4 v = *reinterpret_cast<const float4*>(
                &Asrc[(size_t)(n0 + r) * DIM + kk0 + c4]);
            As[c4 + 0][r] = v.x; As[c4 + 1][r] = v.y;
            As[c4 + 2][r] = v.z; As[c4 + 3][r] = v.w;
        }
        // Load B tile: 128 rows (e) x 16 cols (k)
#pragma unroll
        for (int i = 0; i < 2; i++) {
            int f = tid + i * 256;
            int r = f >> 2;
            int c4 = (f & 3) * 4;
            float4 v = *reinterpret_cast<const float4*>(
                &B[(size_t)(e0 + r) * K + kt + c4]);
            Bs[c4 + 0][r] = v.x; Bs[c4 + 1][r] = v.y;
            Bs[c4 + 2][r] = v.z; Bs[c4 + 3][r] = v.w;
        }
        __syncthreads();

#pragma unroll
        for (int kk = 0; kk < BKK; kk++) {
            float4 a0v = *reinterpret_cast<const float4*>(&As[kk][ty * TM]);
            float4 a1v = *reinterpret_cast<const float4*>(&As[kk][ty * TM + 4]);
            float4 b0v = *reinterpret_cast<const float4*>(&Bs[kk][tx * TN]);
            float4 b1v = *reinterpret_cast<const float4*>(&Bs[kk][tx * TN + 4]);
            float a[TM] = {a0v.x, a0v.y, a0v.z, a0v.w, a1v.x, a1v.y, a1v.z, a1v.w};
            float b[TN] = {b0v.x, b0v.y, b0v.z, b0v.w, b1v.x, b1v.y, b1v.z, b1v.w};
#pragma unroll
            for (int i = 0; i < TM; i++)
#pragma unroll
                for (int j = 0; j < TN; j++)
                    acc[i][j] = fmaf(a[i], b[j], acc[i][j]);
        }
        __syncthreads();
    }

#pragma unroll
    for (int i = 0; i < TM; i++) {
        int n = n0 + ty * TM + i;
#pragma unroll
        for (int j = 0; j < TN; j += 4) {
            int e = e0 + tx * TN + j;
            float4 bv = *reinterpret_cast<const float4*>(&bias[e]);
            float4 o;
            o.x = acc[i][j + 0] + bv.x;
            o.y = acc[i][j + 1] + bv.y;
            o.z = acc[i][j + 2] + bv.z;
            o.w = acc[i][j + 3] + bv.w;
            *reinterpret_cast<float4*>(&C[(size_t)n * DIM + e]) = o;
        }
    }
}

// ---------------------------------------------------------------------------
// Retrieval: per row, sim[m] = <Q[n], mem[m]>, top-3, softmax, weighted gather.
// One block of 256 threads per row.
// ---------------------------------------------------------------------------
__global__ void __launch_bounds__(256) retrieve_kernel(
    const float* __restrict__ Q,
    const float* __restrict__ mem,      // [64, 1024]
    float* __restrict__ mem_out)
{
    const int n = blockIdx.x;
    const int tid = threadIdx.x;
    const int lane = tid & 31;
    const int warp = tid >> 5;

    __shared__ float4 qs[DIM / 4];
    __shared__ float sim[MSL];
    __shared__ float wgt[KTOP];
    __shared__ int   sidx[KTOP];

    qs[tid] = reinterpret_cast<const float4*>(Q + (size_t)n * DIM)[tid];
    __syncthreads();

    const float4* qf4 = qs;
    // 8 warps x 8 memory rows each
#pragma unroll
    for (int r = 0; r < 8; r++) {
        int m = warp * 8 + r;
        const float4* mrow = reinterpret_cast<const float4*>(mem + (size_t)m * DIM);
        float s = 0.f;
#pragma unroll
        for (int i = 0; i < 8; i++) {
            int d = lane + i * 32;          // float4 index, 256 total
            float4 a = qf4[d];
            float4 b = mrow[d];
            s = fmaf(a.x, b.x, s);
            s = fmaf(a.y, b.y, s);
            s = fmaf(a.z, b.z, s);
            s = fmaf(a.w, b.w, s);
        }
#pragma unroll
        for (int o = 16; o; o >>= 1) s += __shfl_xor_sync(0xffffffffu, s, o);
        if (lane == 0) sim[m] = s;
    }
    __syncthreads();

    if (tid == 0) {
        float v0 = -3.4e38f, v1 = -3.4e38f, v2 = -3.4e38f;
        int i0 = 0, i1 = 0, i2 = 0;
        for (int m = 0; m < MSL; m++) {
            float v = sim[m];
            if (v > v0)      { v2 = v1; i2 = i1; v1 = v0; i1 = i0; v0 = v; i0 = m; }
            else if (v > v1) { v2 = v1; i2 = i1; v1 = v;  i1 = m; }
            else if (v > v2) { v2 = v;  i2 = m; }
        }
        float e0 = 1.f;                 // exp(v0 - v0)
        float e1 = __expf(v1 - v0);
        float e2 = __expf(v2 - v0);
        float inv = 1.f / (e0 + e1 + e2);
        wgt[0] = e0 * inv; wgt[1] = e1 * inv; wgt[2] = e2 * inv;
        sidx[0] = i0; sidx[1] = i1; sidx[2] = i2;
    }
    __syncthreads();

    const float w0 = wgt[0], w1 = wgt[1], w2 = wgt[2];
    const float4* m0 = reinterpret_cast<const float4*>(mem + (size_t)sidx[0] * DIM);
    const float4* m1 = reinterpret_cast<const float4*>(mem + (size_t)sidx[1] * DIM);
    const float4* m2 = reinterpret_cast<const float4*>(mem + (size_t)sidx[2] * DIM);
    float4 a = m0[tid], b = m1[tid], c = m2[tid];
    float4 o;
    o.x = w0 * a.x + w1 * b.x + w2 * c.x;
    o.y = w0 * a.y + w1 * b.y + w2 * c.y;
    o.z = w0 * a.z + w1 * b.z + w2 * c.z;
    o.w = w0 * a.w + w1 * b.w + w2 * c.w;
    reinterpret_cast<float4*>(mem_out + (size_t)n * DIM)[tid] = o;
}

// ---------------------------------------------------------------------------
// LayerNorm + ReLU, one block of 256 threads per row (4 elems per thread).
// ---------------------------------------------------------------------------
__global__ void __launch_bounds__(256) ln_relu_kernel(
    const float* __restrict__ H,
    const float* __restrict__ gamma,
    const float* __restrict__ beta,
    float* __restrict__ out)
{
    const int n = blockIdx.x;
    const int tid = threadIdx.x;
    const int lane = tid & 31;
    const int warp = tid >> 5;

    float4 v = reinterpret_cast<const float4*>(H + (size_t)n * DIM)[tid];
    float s  = v.x + v.y + v.z + v.w;
    float ss = v.x * v.x + v.y * v.y + v.z * v.z + v.w * v.w;

#pragma unroll
    for (int o = 16; o; o >>= 1) {
        s  += __shfl_xor_sync(0xffffffffu, s, o);
        ss += __shfl_xor_sync(0xffffffffu, ss, o);
    }
    __shared__ float sh_s[8], sh_ss[8];
    if (lane == 0) { sh_s[warp] = s; sh_ss[warp] = ss; }
    __syncthreads();
    if (warp == 0) {
        s  = (lane < 8) ? sh_s[lane]  : 0.f;
        ss = (lane < 8) ? sh_ss[lane] : 0.f;
#pragma unroll
        for (int o = 4; o; o >>= 1) {
            s  += __shfl_xor_sync(0xffffffffu, s, o);
            ss += __shfl_xor_sync(0xffffffffu, ss, o);
        }
        if (lane == 0) { sh_s[0] = s; sh_ss[0] = ss; }
    }
    __syncthreads();

    const float mean = sh_s[0] * (1.f / DIM);
    const float var  = sh_ss[0] * (1.f / DIM) - mean * mean;
    const float rstd = rsqrtf(var + LN_EPS);

    float4 g = reinterpret_cast<const float4*>(gamma)[tid];
    float4 bb = reinterpret_cast<const float4*>(beta)[tid];
    float4 o;
    o.x = fmaxf((v.x - mean) * rstd * g.x + bb.x, 0.f);
    o.y = fmaxf((v.y - mean) * rstd * g.y + bb.y, 0.f);
    o.z = fmaxf((v.z - mean) * rstd * g.z + bb.z, 0.f);
    o.w = fmaxf((v.w - mean) * rstd * g.w + bb.w, 0.f);
    reinterpret_cast<float4*>(out + (size_t)n * DIM)[tid] = o;
}

// ---------------------------------------------------------------------------
extern "C" void kernel_launch(void* const* d_in, const int* in_sizes, int n_in,
                              void* d_out, int out_size)
{
    const float* x      = (const float*)d_in[0];   // [8,2048,1024]
    const float* memory = (const float*)d_in[1];   // [64,1024]
    const float* Wq     = (const float*)d_in[2];   // [1024,1024] (e,d)
    const float* bq     = (const float*)d_in[3];   // [1024]
    const float* Wf     = (const float*)d_in[4];   // [1024,2048] (d,c)
    const float* bf     = (const float*)d_in[5];   // [1024]
    const float* gamma  = (const float*)d_in[6];   // [1024]
    const float* beta   = (const float*)d_in[7];   // [1024]
    float* out = (float*)d_out;

    float *Q, *MO, *H;
    cudaGetSymbolAddress((void**)&Q,  g_Q);
    cudaGetSymbolAddress((void**)&MO, g_MO);
    cudaGetSymbolAddress((void**)&H,  g_H);

    dim3 grid_gemm(DIM / BN, NTOK / BM);   // (8, 128)

    // 1) Q = x @ Wq^T + bq
    sgemm_kernel<<<grid_gemm, 256>>>(x, nullptr, Wq, bq, Q, DIM);
    // 2) retrieval: sim -> top3 -> softmax -> weighted memory gather
    retrieve_kernel<<<NTOK, 256>>>(Q, memory, MO);
    // 3) H = [x, MO] @ Wf^T + bf
    sgemm_kernel<<<grid_gemm, 256>>>(x, MO, Wf, bf, H, 2 * DIM);
    // 4) out = relu(LN(H) * gamma + beta)
    ln_relu_kernel<<<NTOK, 256>>>(H, gamma, beta, out);
}

// round 3
// speedup vs baseline: 2.2450x; 2.2450x over previous
#include <cuda_runtime.h>
#include <cuda_bf16.h>
#include <math.h>
#include <stdint.h>

#define NTOK (8 * 2048)      // 16384 rows
#define DIM  1024
#define MSL  64
#define KTOP 3
#define LN_EPS 1e-5f

// ---------------- scratch (allocation-free rule: __device__ globals) -------
__device__ __nv_bfloat16 g_xh[(size_t)NTOK * DIM];
__device__ __nv_bfloat16 g_xl[(size_t)NTOK * DIM];
__device__ __nv_bfloat16 g_moh[(size_t)NTOK * DIM];
__device__ __nv_bfloat16 g_mol[(size_t)NTOK * DIM];
__device__ __nv_bfloat16 g_wqh[(size_t)DIM * DIM];
__device__ __nv_bfloat16 g_wql[(size_t)DIM * DIM];
__device__ __nv_bfloat16 g_wfh[(size_t)DIM * 2 * DIM];
__device__ __nv_bfloat16 g_wfl[(size_t)DIM * 2 * DIM];
__device__ float g_Q[(size_t)NTOK * DIM];
__device__ float g_H[(size_t)NTOK * DIM];

// ---------------- helpers ----------------------------------------------------
__device__ __forceinline__ uint32_t smem_u32(const void* p) {
    uint32_t a;
    asm("{ .reg .u64 t; cvta.to.shared.u64 t, %1; cvt.u32.u64 %0, t; }" : "=r"(a) : "l"(p));
    return a;
}

__device__ __forceinline__ void cpasync16(uint32_t s, const void* g) {
    asm volatile("cp.async.cg.shared.global [%0], [%1], 16;" :: "r"(s), "l"(g));
}
__device__ __forceinline__ void cp_commit() {
    asm volatile("cp.async.commit_group;");
}
__device__ __forceinline__ void cp_wait1() {
    asm volatile("cp.async.wait_group 1;");
}

__device__ __forceinline__ void ldsm4(uint32_t* t, uint32_t addr) {
    asm volatile("ldmatrix.sync.aligned.m8n8.x4.shared.b16 {%0,%1,%2,%3}, [%4];"
        : "=r"(t[0]), "=r"(t[1]), "=r"(t[2]), "=r"(t[3]) : "r"(addr));
}

__device__ __forceinline__ void mma16816(float* d, const uint32_t* a,
                                         uint32_t b0, uint32_t b1) {
    asm volatile(
        "mma.sync.aligned.m16n8k16.row.col.f32.bf16.bf16.f32 "
        "{%0,%1,%2,%3}, {%4,%5,%6,%7}, {%8,%9}, {%0,%1,%2,%3};"
        : "+f"(d[0]), "+f"(d[1]), "+f"(d[2]), "+f"(d[3])
        : "r"(a[0]), "r"(a[1]), "r"(a[2]), "r"(a[3]), "r"(b0), "r"(b1));
}

// XOR swizzle: 128-row x 32-col bf16 tile, 16B chunks. row pitch 64B.
// phys = row*64 + ((c ^ ((row>>1)&3)) * 16)  -> ldmatrix 8-row groups hit
// distinct (row&1, chunk) bank groups => conflict-free.
__device__ __forceinline__ uint32_t sw(uint32_t row, uint32_t c) {
    return row * 64u + ((c ^ ((row >> 1) & 3u)) << 4);
}

// ---------------- split fp32 -> (bf16 hi, bf16 lo) --------------------------
__global__ void __launch_bounds__(256) split_kernel(
    const float4* __restrict__ in, __nv_bfloat162* __restrict__ hi,
    __nv_bfloat162* __restrict__ lo, int n4)
{
    int i = blockIdx.x * 256 + threadIdx.x;
    if (i >= n4) return;
    float4 v = in[i];
    __nv_bfloat16 hx = __float2bfloat16_rn(v.x);
    __nv_bfloat16 hy = __float2bfloat16_rn(v.y);
    __nv_bfloat16 hz = __float2bfloat16_rn(v.z);
    __nv_bfloat16 hw = __float2bfloat16_rn(v.w);
    __nv_bfloat162 h0; h0.x = hx; h0.y = hy;
    __nv_bfloat162 h1; h1.x = hz; h1.y = hw;
    __nv_bfloat162 l0;
    l0.x = __float2bfloat16_rn(v.x - __bfloat162float(hx));
    l0.y = __float2bfloat16_rn(v.y - __bfloat162float(hy));
    __nv_bfloat162 l1;
    l1.x = __float2bfloat16_rn(v.z - __bfloat162float(hz));
    l1.y = __float2bfloat16_rn(v.w - __bfloat162float(hw));
    hi[2 * i] = h0; hi[2 * i + 1] = h1;
    lo[2 * i] = l0; lo[2 * i + 1] = l1;
}

// ---------------- bf16x3 HMMA GEMM -------------------------------------------
// C[n,e] = sum_k A[n,k]*B[e,k] + bias[e]
// A split hi/lo, two K-sources (x then mem_out). B split hi/lo, [E][K] row-major.
// CTA tile 128(M) x 128(N), BK=32, 256 threads = 8 warps (2M x 4N), warp 64x32.
#define GBM 128
#define GBN 128
#define GBK 32
#define TILE_B 8192u                      // one 128x32 bf16 tile
#define OFF_AH 0u
#define OFF_AL (TILE_B)
#define OFF_BH (2u * TILE_B)
#define OFF_BL (3u * TILE_B)
#define STAGE_B (4u * TILE_B)             // 32 KB
#define GEMM_SMEM (2u * STAGE_B)          // 64 KB

__global__ void __launch_bounds__(256, 1) gemm_bf16x3_kernel(
    const __nv_bfloat16* __restrict__ A0h, const __nv_bfloat16* __restrict__ A0l,
    const __nv_bfloat16* __restrict__ A1h, const __nv_bfloat16* __restrict__ A1l,
    const __nv_bfloat16* __restrict__ Bh,  const __nv_bfloat16* __restrict__ Bl,
    const float* __restrict__ bias,
    float* __restrict__ C,
    int K)
{
    extern __shared__ char smem[];
    const uint32_t sb = smem_u32(smem);
    const int tid = threadIdx.x;
    const int wid = tid >> 5;
    const int lane = tid & 31;
    const int n0 = blockIdx.y * GBM;
    const int e0 = blockIdx.x * GBN;
    const int nchunk = K / GBK;

    const uint32_t warp_m = (uint32_t)(wid >> 2) * 64u;   // 0 or 64
    const uint32_t warp_n = (uint32_t)(wid & 3) * 32u;    // 0,32,64,96

    float acc[4][4][4];
#pragma unroll
    for (int mt = 0; mt < 4; mt++)
#pragma unroll
        for (int nt = 0; nt < 4; nt++)
#pragma unroll
            for (int j = 0; j < 4; j++) acc[mt][nt][j] = 0.f;

    // ---- stage loader ----
    auto load_stage = [&](int i, int s) {
        const int kt = i * GBK;
        const __nv_bfloat16* ah; const __nv_bfloat16* al; int kc;
        if (kt < DIM) { ah = A0h; al = A0l; kc = kt; }
        else          { ah = A1h; al = A1l; kc = kt - DIM; }
        const uint32_t sbase = sb + (uint32_t)s * STAGE_B;
#pragma unroll
        for (int j = 0; j < 2; j++) {
            int g = tid + j * 256;
            uint32_t r = (uint32_t)(g >> 2);
            uint32_t c = (uint32_t)(g & 3);
            uint32_t so = sw(r, c);
            cpasync16(sbase + OFF_AH + so, ah + (size_t)(n0 + r) * DIM + kc + c * 8);
            cpasync16(sbase + OFF_AL + so, al + (size_t)(n0 + r) * DIM + kc + c * 8);
            cpasync16(sbase + OFF_BH + so, Bh + (size_t)(e0 + r) * K + kt + c * 8);
            cpasync16(sbase + OFF_BL + so, Bl + (size_t)(e0 + r) * K + kt + c * 8);
        }
    };

    load_stage(0, 0);
    cp_commit();

    for (int i = 0; i < nchunk; i++) {
        const int s = i & 1;
        if (i + 1 < nchunk) load_stage(i + 1, s ^ 1);
        cp_commit();
        cp_wait1();
        __syncthreads();

        const uint32_t base = sb + (uint32_t)s * STAGE_B;
#pragma unroll
        for (int k16 = 0; k16 < 2; k16++) {
            // A fragments (hi and lo): row = warp_m + mt*16 + (lane&15),
            // k-chunk = 2*k16 + (lane>>4)
            uint32_t ah[4][4], al[4][4];
            const uint32_t arow = (uint32_t)(lane & 15);
            const uint32_t acnk = (uint32_t)(2 * k16 + (lane >> 4));
#pragma unroll
            for (int mt = 0; mt < 4; mt++) {
                uint32_t so = sw(warp_m + (uint32_t)mt * 16u + arow, acnk);
                ldsm4(ah[mt], base + OFF_AH + so);
                ldsm4(al[mt], base + OFF_AL + so);
            }
            // B fragments: two ldsm.x4 cover 4 n8 tiles (hi and lo)
            uint32_t bh[4][2], bl[4][2];
            const uint32_t brow0 = (uint32_t)((lane & 7) + ((lane >> 4) & 1) * 8);
            const uint32_t bcnk  = (uint32_t)(2 * k16 + ((lane >> 3) & 1));
#pragma unroll
            for (int half = 0; half < 2; half++) {
                uint32_t so = sw(warp_n + (uint32_t)half * 16u + brow0, bcnk);
                uint32_t t[4];
                ldsm4(t, base + OFF_BH + so);
                bh[2 * half][0] = t[0]; bh[2 * half][1] = t[1];
                bh[2 * half + 1][0] = t[2]; bh[2 * half + 1][1] = t[3];
                ldsm4(t, base + OFF_BL + so);
                bl[2 * half][0] = t[0]; bl[2 * half][1] = t[1];
                bl[2 * half + 1][0] = t[2]; bl[2 * half + 1][1] = t[3];
            }
#pragma unroll
            for (int mt = 0; mt < 4; mt++) {
#pragma unroll
                for (int nt = 0; nt < 4; nt++) {
                    mma16816(acc[mt][nt], ah[mt], bh[nt][0], bh[nt][1]);
                    mma16816(acc[mt][nt], ah[mt], bl[nt][0], bl[nt][1]);
                    mma16816(acc[mt][nt], al[mt], bh[nt][0], bh[nt][1]);
                }
            }
        }
        __syncthreads();
    }

    // ---- epilogue: d0,d1 -> row l/4; d2,d3 -> row l/4+8; cols (l%4)*2 ----
#pragma unroll
    for (int mt = 0; mt < 4; mt++) {
#pragma unroll
        for (int nt = 0; nt < 4; nt++) {
            int row = n0 + (int)warp_m + mt * 16 + (lane >> 2);
            int col = e0 + (int)warp_n + nt * 8 + (lane & 3) * 2;
            float b0 = bias[col], b1 = bias[col + 1];
            float2 v0; v0.x = acc[mt][nt][0] + b0; v0.y = acc[mt][nt][1] + b1;
            float2 v1; v1.x = acc[mt][nt][2] + b0; v1.y = acc[mt][nt][3] + b1;
            *reinterpret_cast<float2*>(&C[(size_t)row * DIM + col]) = v0;
            *reinterpret_cast<float2*>(&C[(size_t)(row + 8) * DIM + col]) = v1;
        }
    }
}

// ---------------- retrieval: sim -> top3 -> softmax -> gather ---------------
__global__ void __launch_bounds__(256) retrieve_kernel(
    const float* __restrict__ Q,
    const float* __restrict__ mem,
    __nv_bfloat162* __restrict__ moh,
    __nv_bfloat162* __restrict__ mol)
{
    const int n = blockIdx.x;
    const int tid = threadIdx.x;
    const int lane = tid & 31;
    const int warp = tid >> 5;

    __shared__ float4 qs[DIM / 4];
    __shared__ float sim[MSL];
    __shared__ float wgt[KTOP];
    __shared__ int   sidx[KTOP];

    qs[tid] = reinterpret_cast<const float4*>(Q + (size_t)n * DIM)[tid];
    __syncthreads();

#pragma unroll
    for (int r = 0; r < 8; r++) {
        int m = warp * 8 + r;
        const float4* mrow = reinterpret_cast<const float4*>(mem + (size_t)m * DIM);
        float s = 0.f;
#pragma unroll
        for (int i = 0; i < 8; i++) {
            int d = lane + i * 32;
            float4 a = qs[d];
            float4 b = mrow[d];
            s = fmaf(a.x, b.x, s); s = fmaf(a.y, b.y, s);
            s = fmaf(a.z, b.z, s); s = fmaf(a.w, b.w, s);
        }
#pragma unroll
        for (int o = 16; o; o >>= 1) s += __shfl_xor_sync(0xffffffffu, s, o);
        if (lane == 0) sim[m] = s;
    }
    __syncthreads();

    if (tid == 0) {
        float v0 = -3.4e38f, v1 = -3.4e38f, v2 = -3.4e38f;
        int i0 = 0, i1 = 0, i2 = 0;
        for (int m = 0; m < MSL; m++) {
            float v = sim[m];
            if (v > v0)      { v2 = v1; i2 = i1; v1 = v0; i1 = i0; v0 = v; i0 = m; }
            else if (v > v1) { v2 = v1; i2 = i1; v1 = v;  i1 = m; }
            else if (v > v2) { v2 = v;  i2 = m; }
        }
        float e1 = __expf(v1 - v0);
        float e2 = __expf(v2 - v0);
        float inv = 1.f / (1.f + e1 + e2);
        wgt[0] = inv; wgt[1] = e1 * inv; wgt[2] = e2 * inv;
        sidx[0] = i0; sidx[1] = i1; sidx[2] = i2;
    }
    __syncthreads();

    const float w0 = wgt[0], w1 = wgt[1], w2 = wgt[2];
    const float4* m0 = reinterpret_cast<const float4*>(mem + (size_t)sidx[0] * DIM);
    const float4* m1 = reinterpret_cast<const float4*>(mem + (size_t)sidx[1] * DIM);
    const float4* m2 = reinterpret_cast<const float4*>(mem + (size_t)sidx[2] * DIM);
    float4 a = m0[tid], b = m1[tid], c = m2[tid];
    float4 o;
    o.x = w0 * a.x + w1 * b.x + w2 * c.x;
    o.y = w0 * a.y + w1 * b.y + w2 * c.y;
    o.z = w0 * a.z + w1 * b.z + w2 * c.z;
    o.w = w0 * a.w + w1 * b.w + w2 * c.w;

    __nv_bfloat16 hx = __float2bfloat16_rn(o.x);
    __nv_bfloat16 hy = __float2bfloat16_rn(o.y);
    __nv_bfloat16 hz = __float2bfloat16_rn(o.z);
    __nv_bfloat16 hw = __float2bfloat16_rn(o.w);
    __nv_bfloat162 h0; h0.x = hx; h0.y = hy;
    __nv_bfloat162 h1; h1.x = hz; h1.y = hw;
    __nv_bfloat162 l0;
    l0.x = __float2bfloat16_rn(o.x - __bfloat162float(hx));
    l0.y = __float2bfloat16_rn(o.y - __bfloat162float(hy));
    __nv_bfloat162 l1;
    l1.x = __float2bfloat16_rn(o.z - __bfloat162float(hz));
    l1.y = __float2bfloat16_rn(o.w - __bfloat162float(hw));
    size_t base = (size_t)n * (DIM / 2) + 2 * tid;
    moh[base] = h0; moh[base + 1] = h1;
    mol[base] = l0; mol[base + 1] = l1;
}

// ---------------- LayerNorm + ReLU ------------------------------------------
__global__ void __launch_bounds__(256) ln_relu_kernel(
    const float* __restrict__ H,
    const float* __restrict__ gamma,
    const float* __restrict__ beta,
    float* __restrict__ out)
{
    const int n = blockIdx.x;
    const int tid = threadIdx.x;
    const int lane = tid & 31;
    const int warp = tid >> 5;

    float4 v = reinterpret_cast<const float4*>(H + (size_t)n * DIM)[tid];
    float s  = v.x + v.y + v.z + v.w;
    float ss = v.x * v.x + v.y * v.y + v.z * v.z + v.w * v.w;
#pragma unroll
    for (int o = 16; o; o >>= 1) {
        s  += __shfl_xor_sync(0xffffffffu, s, o);
        ss += __shfl_xor_sync(0xffffffffu, ss, o);
    }
    __shared__ float sh_s[8], sh_ss[8];
    if (lane == 0) { sh_s[warp] = s; sh_ss[warp] = ss; }
    __syncthreads();
    if (warp == 0) {
        s  = (lane < 8) ? sh_s[lane]  : 0.f;
        ss = (lane < 8) ? sh_ss[lane] : 0.f;
#pragma unroll
        for (int o = 4; o; o >>= 1) {
            s  += __shfl_xor_sync(0xffffffffu, s, o);
            ss += __shfl_xor_sync(0xffffffffu, ss, o);
        }
        if (lane == 0) { sh_s[0] = s; sh_ss[0] = ss; }
    }
    __syncthreads();

    const float mean = sh_s[0] * (1.f / DIM);
    const float var  = sh_ss[0] * (1.f / DIM) - mean * mean;
    const float rstd = rsqrtf(var + LN_EPS);
    float4 g = reinterpret_cast<const float4*>(gamma)[tid];
    float4 bb = reinterpret_cast<const float4*>(beta)[tid];
    float4 o;
    o.x = fmaxf((v.x - mean) * rstd * g.x + bb.x, 0.f);
    o.y = fmaxf((v.y - mean) * rstd * g.y + bb.y, 0.f);
    o.z = fmaxf((v.z - mean) * rstd * g.z + bb.z, 0.f);
    o.w = fmaxf((v.w - mean) * rstd * g.w + bb.w, 0.f);
    reinterpret_cast<float4*>(out + (size_t)n * DIM)[tid] = o;
}

// ---------------- host --------------------------------------------------------
extern "C" void kernel_launch(void* const* d_in, const int* in_sizes, int n_in,
                              void* d_out, int out_size)
{
    const float* x      = (const float*)d_in[0];
    const float* memory = (const float*)d_in[1];
    const float* Wq     = (const float*)d_in[2];
    const float* bq     = (const float*)d_in[3];
    const float* Wf     = (const float*)d_in[4];
    const float* bf     = (const float*)d_in[5];
    const float* gamma  = (const float*)d_in[6];
    const float* beta   = (const float*)d_in[7];
    float* out = (float*)d_out;

    void *xh, *xl, *moh, *mol, *wqh, *wql, *wfh, *wfl, *Q, *H;
    cudaGetSymbolAddress(&xh,  g_xh);  cudaGetSymbolAddress(&xl,  g_xl);
    cudaGetSymbolAddress(&moh, g_moh); cudaGetSymbolAddress(&mol, g_mol);
    cudaGetSymbolAddress(&wqh, g_wqh); cudaGetSymbolAddress(&wql, g_wql);
    cudaGetSymbolAddress(&wfh, g_wfh); cudaGetSymbolAddress(&wfl, g_wfl);
    cudaGetSymbolAddress(&Q,   g_Q);   cudaGetSymbolAddress(&H,   g_H);

    static bool attr_set = false;
    if (!attr_set) {
        cudaFuncSetAttribute(gemm_bf16x3_kernel,
                             cudaFuncAttributeMaxDynamicSharedMemorySize, GEMM_SMEM);
        attr_set = true;
    }

    // 1) splits
    split_kernel<<<(NTOK * DIM / 4 + 255) / 256, 256>>>(
        (const float4*)x, (__nv_bfloat162*)xh, (__nv_bfloat162*)xl, NTOK * DIM / 4);
    split_kernel<<<(DIM * DIM / 4 + 255) / 256, 256>>>(
        (const float4*)Wq, (__nv_bfloat162*)wqh, (__nv_bfloat162*)wql, DIM * DIM / 4);
    split_kernel<<<(DIM * 2 * DIM / 4 + 255) / 256, 256>>>(
        (const float4*)Wf, (__nv_bfloat162*)wfh, (__nv_bfloat162*)wfl, DIM * 2 * DIM / 4);

    dim3 gg(DIM / GBN, NTOK / GBM);   // (8, 128)

    // 2) Q = x @ Wq^T + bq
    gemm_bf16x3_kernel<<<gg, 256, GEMM_SMEM>>>(
        (const __nv_bfloat16*)xh, (const __nv_bfloat16*)xl,
        (const __nv_bfloat16*)xh, (const __nv_bfloat16*)xl,
        (const __nv_bfloat16*)wqh, (const __nv_bfloat16*)wql,
        bq, (float*)Q, DIM);

    // 3) retrieval -> memory_output splits
    retrieve_kernel<<<NTOK, 256>>>((const float*)Q, memory,
                                   (__nv_bfloat162*)moh, (__nv_bfloat162*)mol);

    // 4) H = [x, MO] @ Wf^T + bf
    gemm_bf16x3_kernel<<<gg, 256, GEMM_SMEM>>>(
        (const __nv_bfloat16*)xh, (const __nv_bfloat16*)xl,
        (const __nv_bfloat16*)moh, (const __nv_bfloat16*)mol,
        (const __nv_bfloat16*)wfh, (const __nv_bfloat16*)wfl,
        bf, (float*)H, 2 * DIM);

    // 5) out = relu(LN(H))
    ln_relu_kernel<<<NTOK, 256>>>((const float*)H, gamma, beta, out);
}

// round 4
// speedup vs baseline: 3.1870x; 1.4196x over previous
#include <cuda_runtime.h>
#include <cuda_fp16.h>
#include <math.h>
#include <stdint.h>

#define NTOK (8 * 2048)      // 16384 rows
#define DIM  1024
#define MSL  64
#define KTOP 3
#define LN_EPS 1e-5f

// ---------------- scratch (allocation-free rule: __device__ globals) -------
__device__ __half g_xh[(size_t)NTOK * DIM];
__device__ __half g_xl[(size_t)NTOK * DIM];
__device__ __half g_moh[(size_t)NTOK * DIM];
__device__ __half g_mol[(size_t)NTOK * DIM];
__device__ __half g_wq[(size_t)DIM * DIM];
__device__ __half g_wf[(size_t)DIM * 2 * DIM];
__device__ float g_Q[(size_t)NTOK * DIM];
__device__ float g_H[(size_t)NTOK * DIM];

// ---------------- helpers ----------------------------------------------------
__device__ __forceinline__ uint32_t smem_u32(const void* p) {
    uint32_t a;
    asm("{ .reg .u64 t; cvta.to.shared.u64 t, %1; cvt.u32.u64 %0, t; }" : "=r"(a) : "l"(p));
    return a;
}
__device__ __forceinline__ void cpasync16(uint32_t s, const void* g) {
    asm volatile("cp.async.cg.shared.global [%0], [%1], 16;" :: "r"(s), "l"(g));
}
__device__ __forceinline__ void cp_commit() {
    asm volatile("cp.async.commit_group;");
}
__device__ __forceinline__ void cp_wait1() {
    asm volatile("cp.async.wait_group 1;");
}
__device__ __forceinline__ void ldsm4(uint32_t* t, uint32_t addr) {
    asm volatile("ldmatrix.sync.aligned.m8n8.x4.shared.b16 {%0,%1,%2,%3}, [%4];"
        : "=r"(t[0]), "=r"(t[1]), "=r"(t[2]), "=r"(t[3]) : "r"(addr));
}
__device__ __forceinline__ void mma16816(float* d, const uint32_t* a,
                                         uint32_t b0, uint32_t b1) {
    asm volatile(
        "mma.sync.aligned.m16n8k16.row.col.f32.f16.f16.f32 "
        "{%0,%1,%2,%3}, {%4,%5,%6,%7}, {%8,%9}, {%0,%1,%2,%3};"
        : "+f"(d[0]), "+f"(d[1]), "+f"(d[2]), "+f"(d[3])
        : "r"(a[0]), "r"(a[1]), "r"(a[2]), "r"(a[3]), "r"(b0), "r"(b1));
}

// XOR swizzle: 128-row x 64-col fp16 tile, 16B chunks (8/row), pitch 128B.
__device__ __forceinline__ uint32_t sw(uint32_t row, uint32_t c) {
    return row * 128u + ((c ^ (row & 7u)) << 4);
}

// ---------------- split fp32 -> (fp16 hi, fp16 lo) ---------------------------
__global__ void __launch_bounds__(256) split_kernel(
    const float4* __restrict__ in, __half2* __restrict__ hi,
    __half2* __restrict__ lo, int n4)
{
    int i = blockIdx.x * 256 + threadIdx.x;
    if (i >= n4) return;
    float4 v = in[i];
    __half hx = __float2half_rn(v.x);
    __half hy = __float2half_rn(v.y);
    __half hz = __float2half_rn(v.z);
    __half hw = __float2half_rn(v.w);
    __half2 h0; h0.x = hx; h0.y = hy;
    __half2 h1; h1.x = hz; h1.y = hw;
    __half2 l0;
    l0.x = __float2half_rn(v.x - __half2float(hx));
    l0.y = __float2half_rn(v.y - __half2float(hy));
    __half2 l1;
    l1.x = __float2half_rn(v.z - __half2float(hz));
    l1.y = __float2half_rn(v.w - __half2float(hw));
    hi[2 * i] = h0; hi[2 * i + 1] = h1;
    lo[2 * i] = l0; lo[2 * i + 1] = l1;
}

// ---------------- round fp32 -> fp16 (weights) --------------------------------
__global__ void __launch_bounds__(256) round_kernel(
    const float4* __restrict__ in, __half2* __restrict__ o, int n4)
{
    int i = blockIdx.x * 256 + threadIdx.x;
    if (i >= n4) return;
    float4 v = in[i];
    __half2 a; a.x = __float2half_rn(v.x); a.y = __float2half_rn(v.y);
    __half2 b; b.x = __float2half_rn(v.z); b.y = __float2half_rn(v.w);
    o[2 * i] = a; o[2 * i + 1] = b;
}

// ---------------- fp16x2 HMMA GEMM --------------------------------------------
// C[n,e] = sum_k A[n,k]*B[e,k] + bias[e]
// A = ah + al (fp16 split, two K-sources), B = fp16 (rounded weights).
// CTA 128(M) x 128(N), BK=64, 256 threads = 8 warps (2M x 4N), warp 64x32.
// 3-stage cp.async ring.
#define GBM 128
#define GBN 128
#define GBK 64
#define TILE_B 16384u                     // one 128x64 fp16 tile
#define OFF_AH 0u
#define OFF_AL (TILE_B)
#define OFF_B  (2u * TILE_B)
#define STAGE_B (3u * TILE_B)             // 48 KB
#define NSTAGE 3
#define GEMM_SMEM (NSTAGE * STAGE_B)      // 144 KB

__global__ void __launch_bounds__(256, 1) gemm_fp16x2_kernel(
    const __half* __restrict__ A0h, const __half* __restrict__ A0l,
    const __half* __restrict__ A1h, const __half* __restrict__ A1l,
    const __half* __restrict__ B,
    const float* __restrict__ bias,
    float* __restrict__ C,
    int K)
{
    extern __shared__ char smem[];
    const uint32_t sb = smem_u32(smem);
    const int tid = threadIdx.x;
    const int wid = tid >> 5;
    const int lane = tid & 31;
    const int n0 = blockIdx.y * GBM;
    const int e0 = blockIdx.x * GBN;
    const int nchunk = K / GBK;

    const uint32_t warp_m = (uint32_t)(wid >> 2) * 64u;   // 0 or 64
    const uint32_t warp_n = (uint32_t)(wid & 3) * 32u;    // 0,32,64,96

    float acc[4][4][4];
#pragma unroll
    for (int mt = 0; mt < 4; mt++)
#pragma unroll
        for (int nt = 0; nt < 4; nt++)
#pragma unroll
            for (int j = 0; j < 4; j++) acc[mt][nt][j] = 0.f;

    auto load_stage = [&](int i, int s) {
        const int kt = i * GBK;
        const __half* ah; const __half* al; int kc;
        if (kt < DIM) { ah = A0h; al = A0l; kc = kt; }
        else          { ah = A1h; al = A1l; kc = kt - DIM; }
        const uint32_t sbase = sb + (uint32_t)s * STAGE_B;
#pragma unroll
        for (int j = 0; j < 4; j++) {
            int g = tid + j * 256;                 // 0..1023
            uint32_t r = (uint32_t)(g >> 3);
            uint32_t c = (uint32_t)(g & 7);
            uint32_t so = sw(r, c);
            cpasync16(sbase + OFF_AH + so, ah + (size_t)(n0 + r) * DIM + kc + c * 8);
            cpasync16(sbase + OFF_AL + so, al + (size_t)(n0 + r) * DIM + kc + c * 8);
            cpasync16(sbase + OFF_B  + so, B  + (size_t)(e0 + r) * K + kt + c * 8);
        }
    };

    load_stage(0, 0); cp_commit();
    load_stage(1, 1); cp_commit();

    for (int i = 0; i < nchunk; i++) {
        cp_wait1();                 // oldest outstanding group (stage i) done
        __syncthreads();            // everyone done with buffer (i+2)%3 too
        if (i + 2 < nchunk) load_stage(i + 2, (i + 2) % NSTAGE);
        cp_commit();                // one group per iteration (may be empty)

        const uint32_t base = sb + (uint32_t)(i % NSTAGE) * STAGE_B;
#pragma unroll
        for (int k16 = 0; k16 < 4; k16++) {
            uint32_t ah[4][4], al[4][4];
            const uint32_t arow = (uint32_t)(lane & 15);
            const uint32_t acnk = (uint32_t)(2 * k16 + (lane >> 4));
#pragma unroll
            for (int mt = 0; mt < 4; mt++) {
                uint32_t so = sw(warp_m + (uint32_t)mt * 16u + arow, acnk);
                ldsm4(ah[mt], base + OFF_AH + so);
                ldsm4(al[mt], base + OFF_AL + so);
            }
            uint32_t bf[4][2];
            const uint32_t brow0 = (uint32_t)((lane & 7) + ((lane >> 4) & 1) * 8);
            const uint32_t bcnk  = (uint32_t)(2 * k16 + ((lane >> 3) & 1));
#pragma unroll
            for (int half = 0; half < 2; half++) {
                uint32_t so = sw(warp_n + (uint32_t)half * 16u + brow0, bcnk);
                uint32_t t[4];
                ldsm4(t, base + OFF_B + so);
                bf[2 * half][0] = t[0];     bf[2 * half][1] = t[1];
                bf[2 * half + 1][0] = t[2]; bf[2 * half + 1][1] = t[3];
            }
#pragma unroll
            for (int mt = 0; mt < 4; mt++) {
#pragma unroll
                for (int nt = 0; nt < 4; nt++) {
                    mma16816(acc[mt][nt], ah[mt], bf[nt][0], bf[nt][1]);
                    mma16816(acc[mt][nt], al[mt], bf[nt][0], bf[nt][1]);
                }
            }
        }
    }

    // ---- epilogue ----
#pragma unroll
    for (int mt = 0; mt < 4; mt++) {
#pragma unroll
        for (int nt = 0; nt < 4; nt++) {
            int row = n0 + (int)warp_m + mt * 16 + (lane >> 2);
            int col = e0 + (int)warp_n + nt * 8 + (lane & 3) * 2;
            float b0 = bias[col], b1 = bias[col + 1];
            float2 v0; v0.x = acc[mt][nt][0] + b0; v0.y = acc[mt][nt][1] + b1;
            float2 v1; v1.x = acc[mt][nt][2] + b0; v1.y = acc[mt][nt][3] + b1;
            *reinterpret_cast<float2*>(&C[(size_t)row * DIM + col]) = v0;
            *reinterpret_cast<float2*>(&C[(size_t)(row + 8) * DIM + col]) = v1;
        }
    }
}

// ---------------- retrieval: sim -> top3 -> softmax -> gather ---------------
__global__ void __launch_bounds__(256) retrieve_kernel(
    const float* __restrict__ Q,
    const float* __restrict__ mem,
    __half2* __restrict__ moh,
    __half2* __restrict__ mol)
{
    const int n = blockIdx.x;
    const int tid = threadIdx.x;
    const int lane = tid & 31;
    const int warp = tid >> 5;

    __shared__ float4 qs[DIM / 4];
    __shared__ float sim[MSL];
    __shared__ float wgt[KTOP];
    __shared__ int   sidx[KTOP];

    qs[tid] = reinterpret_cast<const float4*>(Q + (size_t)n * DIM)[tid];
    __syncthreads();

#pragma unroll
    for (int r = 0; r < 8; r++) {
        int m = warp * 8 + r;
        const float4* mrow = reinterpret_cast<const float4*>(mem + (size_t)m * DIM);
        float s = 0.f;
#pragma unroll
        for (int i = 0; i < 8; i++) {
            int d = lane + i * 32;
            float4 a = qs[d];
            float4 b = mrow[d];
            s = fmaf(a.x, b.x, s); s = fmaf(a.y, b.y, s);
            s = fmaf(a.z, b.z, s); s = fmaf(a.w, b.w, s);
        }
#pragma unroll
        for (int o = 16; o; o >>= 1) s += __shfl_xor_sync(0xffffffffu, s, o);
        if (lane == 0) sim[m] = s;
    }
    __syncthreads();

    if (tid == 0) {
        float v0 = -3.4e38f, v1 = -3.4e38f, v2 = -3.4e38f;
        int i0 = 0, i1 = 0, i2 = 0;
        for (int m = 0; m < MSL; m++) {
            float v = sim[m];
            if (v > v0)      { v2 = v1; i2 = i1; v1 = v0; i1 = i0; v0 = v; i0 = m; }
            else if (v > v1) { v2 = v1; i2 = i1; v1 = v;  i1 = m; }
            else if (v > v2) { v2 = v;  i2 = m; }
        }
        float e1 = __expf(v1 - v0);
        float e2 = __expf(v2 - v0);
        float inv = 1.f / (1.f + e1 + e2);
        wgt[0] = inv; wgt[1] = e1 * inv; wgt[2] = e2 * inv;
        sidx[0] = i0; sidx[1] = i1; sidx[2] = i2;
    }
    __syncthreads();

    const float w0 = wgt[0], w1 = wgt[1], w2 = wgt[2];
    const float4* m0 = reinterpret_cast<const float4*>(mem + (size_t)sidx[0] * DIM);
    const float4* m1 = reinterpret_cast<const float4*>(mem + (size_t)sidx[1] * DIM);
    const float4* m2 = reinterpret_cast<const float4*>(mem + (size_t)sidx[2] * DIM);
    float4 a = m0[tid], b = m1[tid], c = m2[tid];
    float4 o;
    o.x = w0 * a.x + w1 * b.x + w2 * c.x;
    o.y = w0 * a.y + w1 * b.y + w2 * c.y;
    o.z = w0 * a.z + w1 * b.z + w2 * c.z;
    o.w = w0 * a.w + w1 * b.w + w2 * c.w;

    __half hx = __float2half_rn(o.x);
    __half hy = __float2half_rn(o.y);
    __half hz = __float2half_rn(o.z);
    __half hw = __float2half_rn(o.w);
    __half2 h0; h0.x = hx; h0.y = hy;
    __half2 h1; h1.x = hz; h1.y = hw;
    __half2 l0;
    l0.x = __float2half_rn(o.x - __half2float(hx));
    l0.y = __float2half_rn(o.y - __half2float(hy));
    __half2 l1;
    l1.x = __float2half_rn(o.z - __half2float(hz));
    l1.y = __float2half_rn(o.w - __half2float(hw));
    size_t base = (size_t)n * (DIM / 2) + 2 * tid;
    moh[base] = h0; moh[base + 1] = h1;
    mol[base] = l0; mol[base + 1] = l1;
}

// ---------------- LayerNorm + ReLU ------------------------------------------
__global__ void __launch_bounds__(256) ln_relu_kernel(
    const float* __restrict__ H,
    const float* __restrict__ gamma,
    const float* __restrict__ beta,
    float* __restrict__ out)
{
    const int n = blockIdx.x;
    const int tid = threadIdx.x;
    const int lane = tid & 31;
    const int warp = tid >> 5;

    float4 v = reinterpret_cast<const float4*>(H + (size_t)n * DIM)[tid];
    float s  = v.x + v.y + v.z + v.w;
    float ss = v.x * v.x + v.y * v.y + v.z * v.z + v.w * v.w;
#pragma unroll
    for (int o = 16; o; o >>= 1) {
        s  += __shfl_xor_sync(0xffffffffu, s, o);
        ss += __shfl_xor_sync(0xffffffffu, ss, o);
    }
    __shared__ float sh_s[8], sh_ss[8];
    if (lane == 0) { sh_s[warp] = s; sh_ss[warp] = ss; }
    __syncthreads();
    if (warp == 0) {
        s  = (lane < 8) ? sh_s[lane]  : 0.f;
        ss = (lane < 8) ? sh_ss[lane] : 0.f;
#pragma unroll
        for (int o = 4; o; o >>= 1) {
            s  += __shfl_xor_sync(0xffffffffu, s, o);
            ss += __shfl_xor_sync(0xffffffffu, ss, o);
        }
        if (lane == 0) { sh_s[0] = s; sh_ss[0] = ss; }
    }
    __syncthreads();

    const float mean = sh_s[0] * (1.f / DIM);
    const float var  = sh_ss[0] * (1.f / DIM) - mean * mean;
    const float rstd = rsqrtf(var + LN_EPS);
    float4 g = reinterpret_cast<const float4*>(gamma)[tid];
    float4 bb = reinterpret_cast<const float4*>(beta)[tid];
    float4 o;
    o.x = fmaxf((v.x - mean) * rstd * g.x + bb.x, 0.f);
    o.y = fmaxf((v.y - mean) * rstd * g.y + bb.y, 0.f);
    o.z = fmaxf((v.z - mean) * rstd * g.z + bb.z, 0.f);
    o.w = fmaxf((v.w - mean) * rstd * g.w + bb.w, 0.f);
    reinterpret_cast<float4*>(out + (size_t)n * DIM)[tid] = o;
}

// ---------------- host --------------------------------------------------------
extern "C" void kernel_launch(void* const* d_in, const int* in_sizes, int n_in,
                              void* d_out, int out_size)
{
    const float* x      = (const float*)d_in[0];
    const float* memory = (const float*)d_in[1];
    const float* Wq     = (const float*)d_in[2];
    const float* bq     = (const float*)d_in[3];
    const float* Wf     = (const float*)d_in[4];
    const float* bf     = (const float*)d_in[5];
    const float* gamma  = (const float*)d_in[6];
    const float* beta   = (const float*)d_in[7];
    float* out = (float*)d_out;

    void *xh, *xl, *moh, *mol, *wq, *wf, *Q, *H;
    cudaGetSymbolAddress(&xh,  g_xh);  cudaGetSymbolAddress(&xl,  g_xl);
    cudaGetSymbolAddress(&moh, g_moh); cudaGetSymbolAddress(&mol, g_mol);
    cudaGetSymbolAddress(&wq,  g_wq);  cudaGetSymbolAddress(&wf,  g_wf);
    cudaGetSymbolAddress(&Q,   g_Q);   cudaGetSymbolAddress(&H,   g_H);

    static bool attr_set = false;
    if (!attr_set) {
        cudaFuncSetAttribute(gemm_fp16x2_kernel,
                             cudaFuncAttributeMaxDynamicSharedMemorySize, GEMM_SMEM);
        attr_set = true;
    }

    // 1) conversions
    split_kernel<<<(NTOK * DIM / 4 + 255) / 256, 256>>>(
        (const float4*)x, (__half2*)xh, (__half2*)xl, NTOK * DIM / 4);
    round_kernel<<<(DIM * DIM / 4 + 255) / 256, 256>>>(
        (const float4*)Wq, (__half2*)wq, DIM * DIM / 4);
    round_kernel<<<(DIM * 2 * DIM / 4 + 255) / 256, 256>>>(
        (const float4*)Wf, (__half2*)wf, DIM * 2 * DIM / 4);

    dim3 gg(DIM / GBN, NTOK / GBM);   // (8, 128)

    // 2) Q = x @ Wq^T + bq
    gemm_fp16x2_kernel<<<gg, 256, GEMM_SMEM>>>(
        (const __half*)xh, (const __half*)xl,
        (const __half*)xh, (const __half*)xl,
        (const __half*)wq, bq, (float*)Q, DIM);

    // 3) retrieval -> memory_output splits
    retrieve_kernel<<<NTOK, 256>>>((const float*)Q, memory,
                                   (__half2*)moh, (__half2*)mol);

    // 4) H = [x, MO] @ Wf^T + bf
    gemm_fp16x2_kernel<<<gg, 256, GEMM_SMEM>>>(
        (const __half*)xh, (const __half*)xl,
        (const __half*)moh, (const __half*)mol,
        (const __half*)wf, bf, (float*)H, 2 * DIM);

    // 5) out = relu(LN(H))
    ln_relu_kernel<<<NTOK, 256>>>((const float*)H, gamma, beta, out);
}

// round 5
// speedup vs baseline: 3.7161x; 1.1660x over previous
#include <cuda_runtime.h>
#include <cuda_fp16.h>
#include <math.h>
#include <stdint.h>

#define NTOK (8 * 2048)      // 16384 rows
#define DIM  1024
#define NOUT 2048            // fused GEMM output width (Q | Hx)
#define MSL  64
#define KTOP 3
#define LN_EPS 1e-5f

// ---------------- scratch (allocation-free rule: __device__ globals) -------
__device__ __half g_xh[(size_t)NTOK * DIM];
__device__ __half g_xl[(size_t)NTOK * DIM];
__device__ __half g_wcat[(size_t)NOUT * DIM];     // [Wq ; Wf_x] fp16, [2048,1024]
__device__ float g_bias[NOUT];                    // [bq | bf]
__device__ float g_P[(size_t)MSL * DIM];          // memory @ Wf_m^T  (exact fp32)
__device__ float g_C[(size_t)NTOK * NOUT];        // GEMM out: Q | Hx

// ---------------- helpers ----------------------------------------------------
__device__ __forceinline__ uint32_t smem_u32(const void* p) {
    uint32_t a;
    asm("{ .reg .u64 t; cvta.to.shared.u64 t, %1; cvt.u32.u64 %0, t; }" : "=r"(a) : "l"(p));
    return a;
}
__device__ __forceinline__ void cpasync16(uint32_t s, const void* g) {
    asm volatile("cp.async.cg.shared.global [%0], [%1], 16;" :: "r"(s), "l"(g));
}
__device__ __forceinline__ void cp_commit() {
    asm volatile("cp.async.commit_group;");
}
__device__ __forceinline__ void cp_wait1() {
    asm volatile("cp.async.wait_group 1;");
}
__device__ __forceinline__ void ldsm4(uint32_t* t, uint32_t addr) {
    asm volatile("ldmatrix.sync.aligned.m8n8.x4.shared.b16 {%0,%1,%2,%3}, [%4];"
        : "=r"(t[0]), "=r"(t[1]), "=r"(t[2]), "=r"(t[3]) : "r"(addr));
}
__device__ __forceinline__ void mma16816(float* d, const uint32_t* a,
                                         uint32_t b0, uint32_t b1) {
    asm volatile(
        "mma.sync.aligned.m16n8k16.row.col.f32.f16.f16.f32 "
        "{%0,%1,%2,%3}, {%4,%5,%6,%7}, {%8,%9}, {%0,%1,%2,%3};"
        : "+f"(d[0]), "+f"(d[1]), "+f"(d[2]), "+f"(d[3])
        : "r"(a[0]), "r"(a[1]), "r"(a[2]), "r"(a[3]), "r"(b0), "r"(b1));
}

// XOR swizzle: 128-row x 64-col fp16 tile, 16B chunks (8/row), pitch 128B.
__device__ __forceinline__ uint32_t sw(uint32_t row, uint32_t c) {
    return row * 128u + ((c ^ (row & 7u)) << 4);
}

// ---------------- split fp32 -> (fp16 hi, fp16 lo) ---------------------------
__global__ void __launch_bounds__(256) split_kernel(
    const float4* __restrict__ in, __half2* __restrict__ hi,
    __half2* __restrict__ lo, int n4)
{
    int i = blockIdx.x * 256 + threadIdx.x;
    if (i >= n4) return;
    float4 v = in[i];
    __half hx = __float2half_rn(v.x);
    __half hy = __float2half_rn(v.y);
    __half hz = __float2half_rn(v.z);
    __half hw = __float2half_rn(v.w);
    __half2 h0; h0.x = hx; h0.y = hy;
    __half2 h1; h1.x = hz; h1.y = hw;
    __half2 l0;
    l0.x = __float2half_rn(v.x - __half2float(hx));
    l0.y = __float2half_rn(v.y - __half2float(hy));
    __half2 l1;
    l1.x = __float2half_rn(v.z - __half2float(hz));
    l1.y = __float2half_rn(v.w - __half2float(hw));
    hi[2 * i] = h0; hi[2 * i + 1] = h1;
    lo[2 * i] = l0; lo[2 * i + 1] = l1;
}

// ---------------- pack [Wq ; Wf_x] -> fp16, and [bq|bf] ----------------------
__global__ void __launch_bounds__(256) pack_w_kernel(
    const float* __restrict__ Wq,          // [1024,1024]
    const float* __restrict__ Wf,          // [1024,2048]
    const float* __restrict__ bq,
    const float* __restrict__ bf,
    __half2* __restrict__ wcat,            // [2048,1024] fp16
    float* __restrict__ bias)              // [2048]
{
    int i4 = blockIdx.x * 256 + threadIdx.x;      // float4 index over 2048*1024
    if (i4 >= NOUT * DIM / 4) return;
    int e = (i4 * 4) / DIM;
    int c = (i4 * 4) % DIM;
    float4 v;
    if (e < DIM) v = *reinterpret_cast<const float4*>(&Wq[(size_t)e * DIM + c]);
    else         v = *reinterpret_cast<const float4*>(&Wf[(size_t)(e - DIM) * (2 * DIM) + c]);
    __half2 a; a.x = __float2half_rn(v.x); a.y = __float2half_rn(v.y);
    __half2 b; b.x = __float2half_rn(v.z); b.y = __float2half_rn(v.w);
    wcat[2 * i4] = a; wcat[2 * i4 + 1] = b;
    if (i4 < NOUT) bias[i4] = (i4 < DIM) ? bq[i4] : bf[i4 - DIM];
}

// ---------------- P = memory @ Wf[:,1024:]^T  (exact fp32, 64x1024) ----------
__global__ void __launch_bounds__(256) pmat_kernel(
    const float* __restrict__ mem,         // [64,1024]
    const float* __restrict__ Wf,          // [1024,2048]
    float* __restrict__ P)                 // [64,1024]
{
    __shared__ float mrow[DIM];
    const int m = blockIdx.y;
    const int tid = threadIdx.x;
    const int warp = tid >> 5, lane = tid & 31;
    for (int i = tid; i < DIM; i += 256) mrow[i] = mem[(size_t)m * DIM + i];
    __syncthreads();
#pragma unroll
    for (int w = 0; w < 16; w++) {
        int e = blockIdx.x * 128 + warp * 16 + w;
        const float* wrow = Wf + (size_t)e * (2 * DIM) + DIM;
        float s = 0.f;
#pragma unroll
        for (int j = 0; j < 8; j++) {
            int c = lane * 4 + j * 128;
            float4 a = *reinterpret_cast<const float4*>(&mrow[c]);
            float4 b = *reinterpret_cast<const float4*>(&wrow[c]);
            s = fmaf(a.x, b.x, s); s = fmaf(a.y, b.y, s);
            s = fmaf(a.z, b.z, s); s = fmaf(a.w, b.w, s);
        }
#pragma unroll
        for (int o = 16; o; o >>= 1) s += __shfl_xor_sync(0xffffffffu, s, o);
        if (lane == 0) P[(size_t)m * DIM + e] = s;
    }
}

// ---------------- fp16x2 HMMA GEMM: C[n,e] = x[n,:] . Wcat[e,:] + bias[e] ----
// A = xh + xl (fp16 split). CTA 128(M) x 128(N), BK=64, 8 warps, 3-stage ring.
#define GBM 128
#define GBN 128
#define GBK 64
#define TILE_B 16384u
#define OFF_AH 0u
#define OFF_AL (TILE_B)
#define OFF_B  (2u * TILE_B)
#define STAGE_B (3u * TILE_B)
#define NSTAGE 3
#define GEMM_SMEM (NSTAGE * STAGE_B)      // 144 KB

__global__ void __launch_bounds__(256, 1) gemm_fp16x2_kernel(
    const __half* __restrict__ Ah, const __half* __restrict__ Al,
    const __half* __restrict__ B,          // [2048,1024] fp16
    const float* __restrict__ bias,        // [2048]
    float* __restrict__ C)                 // [16384,2048]
{
    extern __shared__ char smem[];
    const uint32_t sb = smem_u32(smem);
    const int tid = threadIdx.x;
    const int wid = tid >> 5;
    const int lane = tid & 31;
    const int n0 = blockIdx.y * GBM;
    const int e0 = blockIdx.x * GBN;
    const int nchunk = DIM / GBK;          // 16

    const uint32_t warp_m = (uint32_t)(wid >> 2) * 64u;
    const uint32_t warp_n = (uint32_t)(wid & 3) * 32u;

    float acc[4][4][4];
#pragma unroll
    for (int mt = 0; mt < 4; mt++)
#pragma unroll
        for (int nt = 0; nt < 4; nt++)
#pragma unroll
            for (int j = 0; j < 4; j++) acc[mt][nt][j] = 0.f;

    auto load_stage = [&](int i, int s) {
        const int kt = i * GBK;
        const uint32_t sbase = sb + (uint32_t)s * STAGE_B;
#pragma unroll
        for (int j = 0; j < 4; j++) {
            int g = tid + j * 256;
            uint32_t r = (uint32_t)(g >> 3);
            uint32_t c = (uint32_t)(g & 7);
            uint32_t so = sw(r, c);
            cpasync16(sbase + OFF_AH + so, Ah + (size_t)(n0 + r) * DIM + kt + c * 8);
            cpasync16(sbase + OFF_AL + so, Al + (size_t)(n0 + r) * DIM + kt + c * 8);
            cpasync16(sbase + OFF_B  + so, B  + (size_t)(e0 + r) * DIM + kt + c * 8);
        }
    };

    load_stage(0, 0); cp_commit();
    load_stage(1, 1); cp_commit();

    for (int i = 0; i < nchunk; i++) {
        cp_wait1();
        __syncthreads();
        if (i + 2 < nchunk) load_stage(i + 2, (i + 2) % NSTAGE);
        cp_commit();

        const uint32_t base = sb + (uint32_t)(i % NSTAGE) * STAGE_B;
#pragma unroll
        for (int k16 = 0; k16 < 4; k16++) {
            uint32_t ah[4][4], al[4][4];
            const uint32_t arow = (uint32_t)(lane & 15);
            const uint32_t acnk = (uint32_t)(2 * k16 + (lane >> 4));
#pragma unroll
            for (int mt = 0; mt < 4; mt++) {
                uint32_t so = sw(warp_m + (uint32_t)mt * 16u + arow, acnk);
                ldsm4(ah[mt], base + OFF_AH + so);
                ldsm4(al[mt], base + OFF_AL + so);
            }
            uint32_t bf[4][2];
            const uint32_t brow0 = (uint32_t)((lane & 7) + ((lane >> 4) & 1) * 8);
            const uint32_t bcnk  = (uint32_t)(2 * k16 + ((lane >> 3) & 1));
#pragma unroll
            for (int half = 0; half < 2; half++) {
                uint32_t so = sw(warp_n + (uint32_t)half * 16u + brow0, bcnk);
                uint32_t t[4];
                ldsm4(t, base + OFF_B + so);
                bf[2 * half][0] = t[0];     bf[2 * half][1] = t[1];
                bf[2 * half + 1][0] = t[2]; bf[2 * half + 1][1] = t[3];
            }
#pragma unroll
            for (int mt = 0; mt < 4; mt++) {
#pragma unroll
                for (int nt = 0; nt < 4; nt++) {
                    mma16816(acc[mt][nt], ah[mt], bf[nt][0], bf[nt][1]);
                    mma16816(acc[mt][nt], al[mt], bf[nt][0], bf[nt][1]);
                }
            }
        }
    }

    // ---- epilogue: C row stride = NOUT ----
#pragma unroll
    for (int mt = 0; mt < 4; mt++) {
#pragma unroll
        for (int nt = 0; nt < 4; nt++) {
            int row = n0 + (int)warp_m + mt * 16 + (lane >> 2);
            int col = e0 + (int)warp_n + nt * 8 + (lane & 3) * 2;
            float b0 = bias[col], b1 = bias[col + 1];
            float2 v0; v0.x = acc[mt][nt][0] + b0; v0.y = acc[mt][nt][1] + b1;
            float2 v1; v1.x = acc[mt][nt][2] + b0; v1.y = acc[mt][nt][3] + b1;
            *reinterpret_cast<float2*>(&C[(size_t)row * NOUT + col]) = v0;
            *reinterpret_cast<float2*>(&C[(size_t)(row + 8) * NOUT + col]) = v1;
        }
    }
}

// ---------------- fused retrieve + P-gather + LayerNorm + ReLU ---------------
// per token: sim from Q (C cols 0..1023), top3 softmax, H = Hx + Σ w_k P[i_k],
// then LN+ReLU -> out. Never materializes MO or H in HBM.
__global__ void __launch_bounds__(256) fused_tail_kernel(
    const float* __restrict__ C,           // [16384,2048] (Q | Hx)
    const float* __restrict__ mem,         // [64,1024]
    const float* __restrict__ P,           // [64,1024]
    const float* __restrict__ gamma,
    const float* __restrict__ beta,
    float* __restrict__ out)
{
    const int n = blockIdx.x;
    const int tid = threadIdx.x;
    const int lane = tid & 31;
    const int warp = tid >> 5;

    __shared__ float4 qs[DIM / 4];
    __shared__ float sim[MSL];
    __shared__ float wgt[KTOP];
    __shared__ int   sidx[KTOP];
    __shared__ float sh_s[8], sh_ss[8];

    qs[tid] = reinterpret_cast<const float4*>(C + (size_t)n * NOUT)[tid];
    __syncthreads();

#pragma unroll
    for (int r = 0; r < 8; r++) {
        int m = warp * 8 + r;
        const float4* mrow = reinterpret_cast<const float4*>(mem + (size_t)m * DIM);
        float s = 0.f;
#pragma unroll
        for (int i = 0; i < 8; i++) {
            int d = lane + i * 32;
            float4 a = qs[d];
            float4 b = mrow[d];
            s = fmaf(a.x, b.x, s); s = fmaf(a.y, b.y, s);
            s = fmaf(a.z, b.z, s); s = fmaf(a.w, b.w, s);
        }
#pragma unroll
        for (int o = 16; o; o >>= 1) s += __shfl_xor_sync(0xffffffffu, s, o);
        if (lane == 0) sim[m] = s;
    }
    __syncthreads();

    if (tid == 0) {
        float v0 = -3.4e38f, v1 = -3.4e38f, v2 = -3.4e38f;
        int i0 = 0, i1 = 0, i2 = 0;
        for (int m = 0; m < MSL; m++) {
            float v = sim[m];
            if (v > v0)      { v2 = v1; i2 = i1; v1 = v0; i1 = i0; v0 = v; i0 = m; }
            else if (v > v1) { v2 = v1; i2 = i1; v1 = v;  i1 = m; }
            else if (v > v2) { v2 = v;  i2 = m; }
        }
        float e1 = __expf(v1 - v0);
        float e2 = __expf(v2 - v0);
        float inv = 1.f / (1.f + e1 + e2);
        wgt[0] = inv; wgt[1] = e1 * inv; wgt[2] = e2 * inv;
        sidx[0] = i0; sidx[1] = i1; sidx[2] = i2;
    }
    __syncthreads();

    const float w0 = wgt[0], w1 = wgt[1], w2 = wgt[2];
    float4 v  = reinterpret_cast<const float4*>(C + (size_t)n * NOUT + DIM)[tid];
    float4 p0 = reinterpret_cast<const float4*>(P + (size_t)sidx[0] * DIM)[tid];
    float4 p1 = reinterpret_cast<const float4*>(P + (size_t)sidx[1] * DIM)[tid];
    float4 p2 = reinterpret_cast<const float4*>(P + (size_t)sidx[2] * DIM)[tid];
    v.x += w0 * p0.x + w1 * p1.x + w2 * p2.x;
    v.y += w0 * p0.y + w1 * p1.y + w2 * p2.y;
    v.z += w0 * p0.z + w1 * p1.z + w2 * p2.z;
    v.w += w0 * p0.w + w1 * p1.w + w2 * p2.w;

    float s  = v.x + v.y + v.z + v.w;
    float ss = v.x * v.x + v.y * v.y + v.z * v.z + v.w * v.w;
#pragma unroll
    for (int o = 16; o; o >>= 1) {
        s  += __shfl_xor_sync(0xffffffffu, s, o);
        ss += __shfl_xor_sync(0xffffffffu, ss, o);
    }
    if (lane == 0) { sh_s[warp] = s; sh_ss[warp] = ss; }
    __syncthreads();
    if (warp == 0) {
        s  = (lane < 8) ? sh_s[lane]  : 0.f;
        ss = (lane < 8) ? sh_ss[lane] : 0.f;
#pragma unroll
        for (int o = 4; o; o >>= 1) {
            s  += __shfl_xor_sync(0xffffffffu, s, o);
            ss += __shfl_xor_sync(0xffffffffu, ss, o);
        }
        if (lane == 0) { sh_s[0] = s; sh_ss[0] = ss; }
    }
    __syncthreads();

    const float mean = sh_s[0] * (1.f / DIM);
    const float var  = sh_ss[0] * (1.f / DIM) - mean * mean;
    const float rstd = rsqrtf(var + LN_EPS);
    float4 g = reinterpret_cast<const float4*>(gamma)[tid];
    float4 bb = reinterpret_cast<const float4*>(beta)[tid];
    float4 o;
    o.x = fmaxf((v.x - mean) * rstd * g.x + bb.x, 0.f);
    o.y = fmaxf((v.y - mean) * rstd * g.y + bb.y, 0.f);
    o.z = fmaxf((v.z - mean) * rstd * g.z + bb.z, 0.f);
    o.w = fmaxf((v.w - mean) * rstd * g.w + bb.w, 0.f);
    reinterpret_cast<float4*>(out + (size_t)n * DIM)[tid] = o;
}

// ---------------- host --------------------------------------------------------
extern "C" void kernel_launch(void* const* d_in, const int* in_sizes, int n_in,
                              void* d_out, int out_size)
{
    const float* x      = (const float*)d_in[0];
    const float* memory = (const float*)d_in[1];
    const float* Wq     = (const float*)d_in[2];
    const float* bq     = (const float*)d_in[3];
    const float* Wf     = (const float*)d_in[4];
    const float* bf     = (const float*)d_in[5];
    const float* gamma  = (const float*)d_in[6];
    const float* beta   = (const float*)d_in[7];
    float* out = (float*)d_out;

    void *xh, *xl, *wcat, *bias, *P, *C;
    cudaGetSymbolAddress(&xh,   g_xh);   cudaGetSymbolAddress(&xl,  g_xl);
    cudaGetSymbolAddress(&wcat, g_wcat); cudaGetSymbolAddress(&bias, g_bias);
    cudaGetSymbolAddress(&P,    g_P);    cudaGetSymbolAddress(&C,   g_C);

    static bool attr_set = false;
    if (!attr_set) {
        cudaFuncSetAttribute(gemm_fp16x2_kernel,
                             cudaFuncAttributeMaxDynamicSharedMemorySize, GEMM_SMEM);
        attr_set = true;
    }

    // 1) conversions + small precomputes
    split_kernel<<<(NTOK * DIM / 4 + 255) / 256, 256>>>(
        (const float4*)x, (__half2*)xh, (__half2*)xl, NTOK * DIM / 4);
    pack_w_kernel<<<(NOUT * DIM / 4 + 255) / 256, 256>>>(
        Wq, Wf, bq, bf, (__half2*)wcat, (float*)bias);
    pmat_kernel<<<dim3(DIM / 128, MSL), 256>>>(memory, Wf, (float*)P);

    // 2) fused GEMM: C = x @ [Wq | Wf_x]^T + [bq|bf]
    dim3 gg(NOUT / GBN, NTOK / GBM);   // (16, 128)
    gemm_fp16x2_kernel<<<gg, 256, GEMM_SMEM>>>(
        (const __half*)xh, (const __half*)xl,
        (const __half*)wcat, (const float*)bias, (float*)C);

    // 3) fused retrieve + gather + LN + ReLU
    fused_tail_kernel<<<NTOK, 256>>>((const float*)C, memory, (const float*)P,
                                     gamma, beta, out);
}

// round 6
// speedup vs baseline: 4.5866x; 1.2342x over previous
#include <cuda_runtime.h>
#include <cuda_fp16.h>
#include <math.h>
#include <stdint.h>

#define NTOK (8 * 2048)      // 16384 rows
#define DIM  1024
#define MSL  64
#define KTOP 3
#define LN_EPS 1e-5f

// ---------------- scratch (allocation-free rule: __device__ globals) -------
__device__ __half g_xh[(size_t)NTOK * DIM];
__device__ __half g_xl[(size_t)NTOK * DIM];
__device__ __half g_wfx[(size_t)DIM * DIM];       // Wf[:, :1024] fp16
__device__ float g_R[(size_t)MSL * DIM];          // mem @ Wq       (exact fp32)
__device__ float g_c[MSL];                        // mem @ bq
__device__ float g_P[(size_t)MSL * DIM];          // mem @ Wf_m^T   (exact fp32)
__device__ float g_sim[(size_t)NTOK * MSL];       // similarity scores
__device__ float g_Hx[(size_t)NTOK * DIM];        // x @ Wf_x^T + bf

// ---------------- helpers ----------------------------------------------------
__device__ __forceinline__ uint32_t smem_u32(const void* p) {
    uint32_t a;
    asm("{ .reg .u64 t; cvta.to.shared.u64 t, %1; cvt.u32.u64 %0, t; }" : "=r"(a) : "l"(p));
    return a;
}
__device__ __forceinline__ void cpasync16(uint32_t s, const void* g) {
    asm volatile("cp.async.cg.shared.global [%0], [%1], 16;" :: "r"(s), "l"(g));
}
__device__ __forceinline__ void cp_commit() {
    asm volatile("cp.async.commit_group;");
}
__device__ __forceinline__ void cp_wait1() {
    asm volatile("cp.async.wait_group 1;");
}
__device__ __forceinline__ void ldsm4(uint32_t* t, uint32_t addr) {
    asm volatile("ldmatrix.sync.aligned.m8n8.x4.shared.b16 {%0,%1,%2,%3}, [%4];"
        : "=r"(t[0]), "=r"(t[1]), "=r"(t[2]), "=r"(t[3]) : "r"(addr));
}
__device__ __forceinline__ void mma16816(float* d, const uint32_t* a,
                                         uint32_t b0, uint32_t b1) {
    asm volatile(
        "mma.sync.aligned.m16n8k16.row.col.f32.f16.f16.f32 "
        "{%0,%1,%2,%3}, {%4,%5,%6,%7}, {%8,%9}, {%0,%1,%2,%3};"
        : "+f"(d[0]), "+f"(d[1]), "+f"(d[2]), "+f"(d[3])
        : "r"(a[0]), "r"(a[1]), "r"(a[2]), "r"(a[3]), "r"(b0), "r"(b1));
}
// XOR swizzle: 128-row x 64-col fp16 tile, 16B chunks (8/row), pitch 128B.
__device__ __forceinline__ uint32_t sw(uint32_t row, uint32_t c) {
    return row * 128u + ((c ^ (row & 7u)) << 4);
}

// ---------------- split fp32 -> (fp16 hi, fp16 lo) ---------------------------
__global__ void __launch_bounds__(256) split_kernel(
    const float4* __restrict__ in, __half2* __restrict__ hi,
    __half2* __restrict__ lo, int n4)
{
    int i = blockIdx.x * 256 + threadIdx.x;
    if (i >= n4) return;
    float4 v = in[i];
    __half hx = __float2half_rn(v.x);
    __half hy = __float2half_rn(v.y);
    __half hz = __float2half_rn(v.z);
    __half hw = __float2half_rn(v.w);
    __half2 h0; h0.x = hx; h0.y = hy;
    __half2 h1; h1.x = hz; h1.y = hw;
    __half2 l0;
    l0.x = __float2half_rn(v.x - __half2float(hx));
    l0.y = __float2half_rn(v.y - __half2float(hy));
    __half2 l1;
    l1.x = __float2half_rn(v.z - __half2float(hz));
    l1.y = __float2half_rn(v.w - __half2float(hw));
    hi[2 * i] = h0; hi[2 * i + 1] = h1;
    lo[2 * i] = l0; lo[2 * i + 1] = l1;
}

// ---------------- pack Wf[:, :1024] -> fp16 -----------------------------------
__global__ void __launch_bounds__(256) pack_wfx_kernel(
    const float* __restrict__ Wf,          // [1024, 2048]
    __half2* __restrict__ wfx)             // [1024, 1024] fp16
{
    int i4 = blockIdx.x * 256 + threadIdx.x;      // float4 idx over 1024x1024
    if (i4 >= DIM * DIM / 4) return;
    int d = i4 >> 8;
    int c = (i4 & 255) * 4;
    float4 v = *reinterpret_cast<const float4*>(&Wf[(size_t)d * (2 * DIM) + c]);
    __half2 a; a.x = __float2half_rn(v.x); a.y = __float2half_rn(v.y);
    __half2 b; b.x = __float2half_rn(v.z); b.y = __float2half_rn(v.w);
    wfx[2 * i4] = a; wfx[2 * i4 + 1] = b;
}

// ---------------- R = mem @ Wq (exact fp32) + c = mem @ bq --------------------
// one block per memory slot m; thread owns 4 output cols (d = tid*4).
__global__ void __launch_bounds__(256) rmat_kernel(
    const float* __restrict__ mem,         // [64, 1024]
    const float* __restrict__ Wq,          // [1024, 1024]  (R[m,d] = sum_e mem[m,e] Wq[e,d])
    const float* __restrict__ bq,          // [1024]
    float* __restrict__ R,                 // [64, 1024]
    float* __restrict__ c)                 // [64]
{
    const int m = blockIdx.x;
    const int tid = threadIdx.x;
    __shared__ float ms[256];
    __shared__ float red[8];

    float4 acc = make_float4(0.f, 0.f, 0.f, 0.f);
    float cpart = 0.f;
    for (int e0 = 0; e0 < DIM; e0 += 256) {
        __syncthreads();
        ms[tid] = mem[(size_t)m * DIM + e0 + tid];
        __syncthreads();
        cpart += bq[e0 + tid] * ms[tid];
#pragma unroll 8
        for (int e = 0; e < 256; e++) {
            float s = ms[e];
            float4 wv = *reinterpret_cast<const float4*>(
                &Wq[(size_t)(e0 + e) * DIM + tid * 4]);
            acc.x = fmaf(s, wv.x, acc.x);
            acc.y = fmaf(s, wv.y, acc.y);
            acc.z = fmaf(s, wv.z, acc.z);
            acc.w = fmaf(s, wv.w, acc.w);
        }
    }
    *reinterpret_cast<float4*>(&R[(size_t)m * DIM + tid * 4]) = acc;
    // reduce cpart -> c[m]
#pragma unroll
    for (int o = 16; o; o >>= 1) cpart += __shfl_xor_sync(0xffffffffu, cpart, o);
    if ((tid & 31) == 0) red[tid >> 5] = cpart;
    __syncthreads();
    if (tid == 0) {
        float s = 0.f;
        for (int w = 0; w < 8; w++) s += red[w];
        c[m] = s;
    }
}

// ---------------- P = memory @ Wf[:,1024:]^T  (exact fp32, 64x1024) ----------
__global__ void __launch_bounds__(256) pmat_kernel(
    const float* __restrict__ mem,         // [64,1024]
    const float* __restrict__ Wf,          // [1024,2048]
    float* __restrict__ P)                 // [64,1024]
{
    __shared__ float mrow[DIM];
    const int m = blockIdx.y;
    const int tid = threadIdx.x;
    const int warp = tid >> 5, lane = tid & 31;
    for (int i = tid; i < DIM; i += 256) mrow[i] = mem[(size_t)m * DIM + i];
    __syncthreads();
#pragma unroll
    for (int w = 0; w < 16; w++) {
        int e = blockIdx.x * 128 + warp * 16 + w;
        const float* wrow = Wf + (size_t)e * (2 * DIM) + DIM;
        float s = 0.f;
#pragma unroll
        for (int j = 0; j < 8; j++) {
            int cc = lane * 4 + j * 128;
            float4 a = *reinterpret_cast<const float4*>(&mrow[cc]);
            float4 b = *reinterpret_cast<const float4*>(&wrow[cc]);
            s = fmaf(a.x, b.x, s); s = fmaf(a.y, b.y, s);
            s = fmaf(a.z, b.z, s); s = fmaf(a.w, b.w, s);
        }
#pragma unroll
        for (int o = 16; o; o >>= 1) s += __shfl_xor_sync(0xffffffffu, s, o);
        if (lane == 0) P[(size_t)m * DIM + e] = s;
    }
}

// ---------------- sim = x @ R^T + c (exact fp32) ------------------------------
// block: 64 tokens x 64 slots, K-tiles of 32. 256 threads, 4x4 acc each.
#define SIM_TOK 64
__global__ void __launch_bounds__(256) sim_kernel(
    const float* __restrict__ x,           // [16384, 1024]
    const float* __restrict__ R,           // [64, 1024]
    const float* __restrict__ c,           // [64]
    float* __restrict__ sim)               // [16384, 64]
{
    __shared__ float xs[64][33];
    __shared__ float rs[64][33];
    __shared__ float cs[64];

    const int n0 = blockIdx.x * SIM_TOK;
    const int tid = threadIdx.x;
    const int tx = tid & 15;               // m group
    const int ty = tid >> 4;               // token group
    if (tid < 64) cs[tid] = c[tid];

    float acc[4][4];
#pragma unroll
    for (int i = 0; i < 4; i++)
#pragma unroll
        for (int j = 0; j < 4; j++) acc[i][j] = 0.f;

    for (int kt = 0; kt < DIM; kt += 32) {
        __syncthreads();
#pragma unroll
        for (int q = 0; q < 2; q++) {
            int f = tid + q * 256;          // 0..511
            int row = f >> 3;
            int c4 = (f & 7) * 4;
            float4 v = *reinterpret_cast<const float4*>(
                &x[(size_t)(n0 + row) * DIM + kt + c4]);
            xs[row][c4] = v.x; xs[row][c4 + 1] = v.y;
            xs[row][c4 + 2] = v.z; xs[row][c4 + 3] = v.w;
            float4 r = *reinterpret_cast<const float4*>(
                &R[(size_t)row * DIM + kt + c4]);
            rs[row][c4] = r.x; rs[row][c4 + 1] = r.y;
            rs[row][c4 + 2] = r.z; rs[row][c4 + 3] = r.w;
        }
        __syncthreads();
#pragma unroll
        for (int kk = 0; kk < 32; kk++) {
            float a[4], b[4];
#pragma unroll
            for (int i = 0; i < 4; i++) a[i] = xs[ty * 4 + i][kk];
#pragma unroll
            for (int j = 0; j < 4; j++) b[j] = rs[tx * 4 + j][kk];
#pragma unroll
            for (int i = 0; i < 4; i++)
#pragma unroll
                for (int j = 0; j < 4; j++)
                    acc[i][j] = fmaf(a[i], b[j], acc[i][j]);
        }
    }
#pragma unroll
    for (int i = 0; i < 4; i++) {
        float4 o;
        o.x = acc[i][0] + cs[tx * 4 + 0];
        o.y = acc[i][1] + cs[tx * 4 + 1];
        o.z = acc[i][2] + cs[tx * 4 + 2];
        o.w = acc[i][3] + cs[tx * 4 + 3];
        *reinterpret_cast<float4*>(
            &sim[(size_t)(n0 + ty * 4 + i) * MSL + tx * 4]) = o;
    }
}

// ---------------- fp16x2 HMMA GEMM: Hx = x @ Wf_x^T + bf ---------------------
#define GBM 128
#define GBN 128
#define GBK 64
#define TILE_B 16384u
#define OFF_AH 0u
#define OFF_AL (TILE_B)
#define OFF_B  (2u * TILE_B)
#define STAGE_B (3u * TILE_B)
#define NSTAGE 3
#define GEMM_SMEM (NSTAGE * STAGE_B)      // 144 KB

__global__ void __launch_bounds__(256, 1) gemm_fp16x2_kernel(
    const __half* __restrict__ Ah, const __half* __restrict__ Al,
    const __half* __restrict__ B,          // [1024,1024] fp16
    const float* __restrict__ bias,        // [1024]
    float* __restrict__ C)                 // [16384,1024]
{
    extern __shared__ char smem[];
    const uint32_t sb = smem_u32(smem);
    const int tid = threadIdx.x;
    const int wid = tid >> 5;
    const int lane = tid & 31;
    const int n0 = blockIdx.y * GBM;
    const int e0 = blockIdx.x * GBN;
    const int nchunk = DIM / GBK;          // 16

    const uint32_t warp_m = (uint32_t)(wid >> 2) * 64u;
    const uint32_t warp_n = (uint32_t)(wid & 3) * 32u;

    float acc[4][4][4];
#pragma unroll
    for (int mt = 0; mt < 4; mt++)
#pragma unroll
        for (int nt = 0; nt < 4; nt++)
#pragma unroll
            for (int j = 0; j < 4; j++) acc[mt][nt][j] = 0.f;

    auto load_stage = [&](int i, int s) {
        const int kt = i * GBK;
        const uint32_t sbase = sb + (uint32_t)s * STAGE_B;
#pragma unroll
        for (int j = 0; j < 4; j++) {
            int g = tid + j * 256;
            uint32_t r = (uint32_t)(g >> 3);
            uint32_t cc = (uint32_t)(g & 7);
            uint32_t so = sw(r, cc);
            cpasync16(sbase + OFF_AH + so, Ah + (size_t)(n0 + r) * DIM + kt + cc * 8);
            cpasync16(sbase + OFF_AL + so, Al + (size_t)(n0 + r) * DIM + kt + cc * 8);
            cpasync16(sbase + OFF_B  + so, B  + (size_t)(e0 + r) * DIM + kt + cc * 8);
        }
    };

    load_stage(0, 0); cp_commit();
    load_stage(1, 1); cp_commit();

    for (int i = 0; i < nchunk; i++) {
        cp_wait1();
        __syncthreads();
        if (i + 2 < nchunk) load_stage(i + 2, (i + 2) % NSTAGE);
        cp_commit();

        const uint32_t base = sb + (uint32_t)(i % NSTAGE) * STAGE_B;
#pragma unroll
        for (int k16 = 0; k16 < 4; k16++) {
            uint32_t ah[4][4], al[4][4];
            const uint32_t arow = (uint32_t)(lane & 15);
            const uint32_t acnk = (uint32_t)(2 * k16 + (lane >> 4));
#pragma unroll
            for (int mt = 0; mt < 4; mt++) {
                uint32_t so = sw(warp_m + (uint32_t)mt * 16u + arow, acnk);
                ldsm4(ah[mt], base + OFF_AH + so);
                ldsm4(al[mt], base + OFF_AL + so);
            }
            uint32_t bf[4][2];
            const uint32_t brow0 = (uint32_t)((lane & 7) + ((lane >> 4) & 1) * 8);
            const uint32_t bcnk  = (uint32_t)(2 * k16 + ((lane >> 3) & 1));
#pragma unroll
            for (int half = 0; half < 2; half++) {
                uint32_t so = sw(warp_n + (uint32_t)half * 16u + brow0, bcnk);
                uint32_t t[4];
                ldsm4(t, base + OFF_B + so);
                bf[2 * half][0] = t[0];     bf[2 * half][1] = t[1];
                bf[2 * half + 1][0] = t[2]; bf[2 * half + 1][1] = t[3];
            }
#pragma unroll
            for (int mt = 0; mt < 4; mt++) {
#pragma unroll
                for (int nt = 0; nt < 4; nt++) {
                    mma16816(acc[mt][nt], ah[mt], bf[nt][0], bf[nt][1]);
                    mma16816(acc[mt][nt], al[mt], bf[nt][0], bf[nt][1]);
                }
            }
        }
    }

#pragma unroll
    for (int mt = 0; mt < 4; mt++) {
#pragma unroll
        for (int nt = 0; nt < 4; nt++) {
            int row = n0 + (int)warp_m + mt * 16 + (lane >> 2);
            int col = e0 + (int)warp_n + nt * 8 + (lane & 3) * 2;
            float b0 = bias[col], b1 = bias[col + 1];
            float2 v0; v0.x = acc[mt][nt][0] + b0; v0.y = acc[mt][nt][1] + b1;
            float2 v1; v1.x = acc[mt][nt][2] + b0; v1.y = acc[mt][nt][3] + b1;
            *reinterpret_cast<float2*>(&C[(size_t)row * DIM + col]) = v0;
            *reinterpret_cast<float2*>(&C[(size_t)(row + 8) * DIM + col]) = v1;
        }
    }
}

// ---------------- tail: top3(sim) -> H = Hx + sum w P -> LN -> ReLU -----------
__global__ void __launch_bounds__(256) tail_kernel(
    const float* __restrict__ sim,         // [16384, 64]
    const float* __restrict__ Hx,          // [16384, 1024]
    const float* __restrict__ P,           // [64, 1024]
    const float* __restrict__ gamma,
    const float* __restrict__ beta,
    float* __restrict__ out)
{
    const int n = blockIdx.x;
    const int tid = threadIdx.x;
    const int lane = tid & 31;
    const int warp = tid >> 5;

    __shared__ float sim_s[MSL];
    __shared__ float wgt[KTOP];
    __shared__ int   sidx[KTOP];
    __shared__ float sh_s[8], sh_ss[8];

    if (tid < MSL) sim_s[tid] = sim[(size_t)n * MSL + tid];
    __syncthreads();

    if (tid == 0) {
        float v0 = -3.4e38f, v1 = -3.4e38f, v2 = -3.4e38f;
        int i0 = 0, i1 = 0, i2 = 0;
        for (int m = 0; m < MSL; m++) {
            float v = sim_s[m];
            if (v > v0)      { v2 = v1; i2 = i1; v1 = v0; i1 = i0; v0 = v; i0 = m; }
            else if (v > v1) { v2 = v1; i2 = i1; v1 = v;  i1 = m; }
            else if (v > v2) { v2 = v;  i2 = m; }
        }
        float e1 = __expf(v1 - v0);
        float e2 = __expf(v2 - v0);
        float inv = 1.f / (1.f + e1 + e2);
        wgt[0] = inv; wgt[1] = e1 * inv; wgt[2] = e2 * inv;
        sidx[0] = i0; sidx[1] = i1; sidx[2] = i2;
    }
    __syncthreads();

    const float w0 = wgt[0], w1 = wgt[1], w2 = wgt[2];
    float4 v  = reinterpret_cast<const float4*>(Hx + (size_t)n * DIM)[tid];
    float4 p0 = reinterpret_cast<const float4*>(P + (size_t)sidx[0] * DIM)[tid];
    float4 p1 = reinterpret_cast<const float4*>(P + (size_t)sidx[1] * DIM)[tid];
    float4 p2 = reinterpret_cast<const float4*>(P + (size_t)sidx[2] * DIM)[tid];
    v.x += w0 * p0.x + w1 * p1.x + w2 * p2.x;
    v.y += w0 * p0.y + w1 * p1.y + w2 * p2.y;
    v.z += w0 * p0.z + w1 * p1.z + w2 * p2.z;
    v.w += w0 * p0.w + w1 * p1.w + w2 * p2.w;

    float s  = v.x + v.y + v.z + v.w;
    float ss = v.x * v.x + v.y * v.y + v.z * v.z + v.w * v.w;
#pragma unroll
    for (int o = 16; o; o >>= 1) {
        s  += __shfl_xor_sync(0xffffffffu, s, o);
        ss += __shfl_xor_sync(0xffffffffu, ss, o);
    }
    if (lane == 0) { sh_s[warp] = s; sh_ss[warp] = ss; }
    __syncthreads();
    if (warp == 0) {
        s  = (lane < 8) ? sh_s[lane]  : 0.f;
        ss = (lane < 8) ? sh_ss[lane] : 0.f;
#pragma unroll
        for (int o = 4; o; o >>= 1) {
            s  += __shfl_xor_sync(0xffffffffu, s, o);
            ss += __shfl_xor_sync(0xffffffffu, ss, o);
        }
        if (lane == 0) { sh_s[0] = s; sh_ss[0] = ss; }
    }
    __syncthreads();

    const float mean = sh_s[0] * (1.f / DIM);
    const float var  = sh_ss[0] * (1.f / DIM) - mean * mean;
    const float rstd = rsqrtf(var + LN_EPS);
    float4 g = reinterpret_cast<const float4*>(gamma)[tid];
    float4 bb = reinterpret_cast<const float4*>(beta)[tid];
    float4 o;
    o.x = fmaxf((v.x - mean) * rstd * g.x + bb.x, 0.f);
    o.y = fmaxf((v.y - mean) * rstd * g.y + bb.y, 0.f);
    o.z = fmaxf((v.z - mean) * rstd * g.z + bb.z, 0.f);
    o.w = fmaxf((v.w - mean) * rstd * g.w + bb.w, 0.f);
    reinterpret_cast<float4*>(out + (size_t)n * DIM)[tid] = o;
}

// ---------------- host --------------------------------------------------------
extern "C" void kernel_launch(void* const* d_in, const int* in_sizes, int n_in,
                              void* d_out, int out_size)
{
    const float* x      = (const float*)d_in[0];
    const float* memory = (const float*)d_in[1];
    const float* Wq     = (const float*)d_in[2];
    const float* bq     = (const float*)d_in[3];
    const float* Wf     = (const float*)d_in[4];
    const float* bf     = (const float*)d_in[5];
    const float* gamma  = (const float*)d_in[6];
    const float* beta   = (const float*)d_in[7];
    float* out = (float*)d_out;

    void *xh, *xl, *wfx, *R, *c, *P, *sim, *Hx;
    cudaGetSymbolAddress(&xh,  g_xh);  cudaGetSymbolAddress(&xl, g_xl);
    cudaGetSymbolAddress(&wfx, g_wfx); cudaGetSymbolAddress(&R,  g_R);
    cudaGetSymbolAddress(&c,   g_c);   cudaGetSymbolAddress(&P,  g_P);
    cudaGetSymbolAddress(&sim, g_sim); cudaGetSymbolAddress(&Hx, g_Hx);

    static bool attr_set = false;
    if (!attr_set) {
        cudaFuncSetAttribute(gemm_fp16x2_kernel,
                             cudaFuncAttributeMaxDynamicSharedMemorySize, GEMM_SMEM);
        attr_set = true;
    }

    // 1) conversions + exact precomputes (all independent)
    split_kernel<<<(NTOK * DIM / 4 + 255) / 256, 256>>>(
        (const float4*)x, (__half2*)xh, (__half2*)xl, NTOK * DIM / 4);
    pack_wfx_kernel<<<DIM * DIM / 4 / 256, 256>>>(Wf, (__half2*)wfx);
    rmat_kernel<<<MSL, 256>>>(memory, Wq, bq, (float*)R, (float*)c);
    pmat_kernel<<<dim3(DIM / 128, MSL), 256>>>(memory, Wf, (float*)P);

    // 2) sim = x @ R^T + c  (exact fp32)
    sim_kernel<<<NTOK / SIM_TOK, 256>>>(x, (const float*)R, (const float*)c,
                                        (float*)sim);

    // 3) Hx = x @ Wf_x^T + bf  (fp16 split tensor-core GEMM)
    dim3 gg(DIM / GBN, NTOK / GBM);   // (8, 128)
    gemm_fp16x2_kernel<<<gg, 256, GEMM_SMEM>>>(
        (const __half*)xh, (const __half*)xl,
        (const __half*)wfx, bf, (float*)Hx);

    // 4) tail: top3/softmax + P gather + LN + ReLU
    tail_kernel<<<NTOK, 256>>>((const float*)sim, (const float*)Hx,
                               (const float*)P, gamma, beta, out);
}

// round 7
// speedup vs baseline: 6.9951x; 1.5251x over previous
#include <cuda_runtime.h>
#include <cuda_fp16.h>
#include <math.h>
#include <stdint.h>

#define NTOK (8 * 2048)      // 16384 rows
#define DIM  1024
#define MSL  64
#define KTOP 3
#define LN_EPS 1e-5f

// ---------------- scratch (allocation-free rule: __device__ globals) -------
__device__ __half g_xh[(size_t)NTOK * DIM];
__device__ __half g_xl[(size_t)NTOK * DIM];
__device__ __half g_wfx[(size_t)DIM * DIM];       // Wf[:, :1024] fp16
__device__ float g_R[(size_t)MSL * DIM];          // mem @ Wq       (exact fp32)
__device__ float g_c[MSL];                        // mem @ bq
__device__ float g_P[(size_t)MSL * DIM];          // mem @ Wf_m^T   (exact fp32)
__device__ float g_sim[(size_t)NTOK * MSL];       // similarity scores
__device__ float g_Hx[(size_t)NTOK * DIM];        // x @ Wf_x^T + bf

// ---------------- helpers ----------------------------------------------------
__device__ __forceinline__ uint32_t smem_u32(const void* p) {
    uint32_t a;
    asm("{ .reg .u64 t; cvta.to.shared.u64 t, %1; cvt.u32.u64 %0, t; }" : "=r"(a) : "l"(p));
    return a;
}
__device__ __forceinline__ void cpasync16(uint32_t s, const void* g) {
    asm volatile("cp.async.cg.shared.global [%0], [%1], 16;" :: "r"(s), "l"(g));
}
__device__ __forceinline__ void cp_commit() {
    asm volatile("cp.async.commit_group;");
}
__device__ __forceinline__ void cp_wait1() {
    asm volatile("cp.async.wait_group 1;");
}
__device__ __forceinline__ void ldsm4(uint32_t* t, uint32_t addr) {
    asm volatile("ldmatrix.sync.aligned.m8n8.x4.shared.b16 {%0,%1,%2,%3}, [%4];"
        : "=r"(t[0]), "=r"(t[1]), "=r"(t[2]), "=r"(t[3]) : "r"(addr));
}
__device__ __forceinline__ void mma16816(float* d, const uint32_t* a,
                                         uint32_t b0, uint32_t b1) {
    asm volatile(
        "mma.sync.aligned.m16n8k16.row.col.f32.f16.f16.f32 "
        "{%0,%1,%2,%3}, {%4,%5,%6,%7}, {%8,%9}, {%0,%1,%2,%3};"
        : "+f"(d[0]), "+f"(d[1]), "+f"(d[2]), "+f"(d[3])
        : "r"(a[0]), "r"(a[1]), "r"(a[2]), "r"(a[3]), "r"(b0), "r"(b1));
}
// XOR swizzle: 128-row x 64-col fp16 tile, 16B chunks (8/row), pitch 128B.
__device__ __forceinline__ uint32_t sw(uint32_t row, uint32_t c) {
    return row * 128u + ((c ^ (row & 7u)) << 4);
}

// ---------------- pack Wf[:, :1024] -> fp16 -----------------------------------
__global__ void __launch_bounds__(256) pack_wfx_kernel(
    const float* __restrict__ Wf,          // [1024, 2048]
    __half2* __restrict__ wfx)             // [1024, 1024] fp16
{
    int i4 = blockIdx.x * 256 + threadIdx.x;      // float4 idx over 1024x1024
    if (i4 >= DIM * DIM / 4) return;
    int d = i4 >> 8;
    int c = (i4 & 255) * 4;
    float4 v = *reinterpret_cast<const float4*>(&Wf[(size_t)d * (2 * DIM) + c]);
    __half2 a; a.x = __float2half_rn(v.x); a.y = __float2half_rn(v.y);
    __half2 b; b.x = __float2half_rn(v.z); b.y = __float2half_rn(v.w);
    wfx[2 * i4] = a; wfx[2 * i4 + 1] = b;
}

// ---------------- R = mem @ Wq (exact fp32) -----------------------------------
// grid (64 col-tiles of 16, 16 m-groups of 4). Wq value reused across 4 m rows.
__global__ void __launch_bounds__(256) rp_r_kernel(
    const float* __restrict__ mem,         // [64, 1024]
    const float* __restrict__ Wq,          // [1024, 1024]  R[m,d]=sum_e mem[m,e]Wq[e,d]
    float* __restrict__ R)                 // [64, 1024]
{
    __shared__ float msf[4 * DIM];         // 4 memory rows
    __shared__ float red[256];
    const int c0 = blockIdx.x * 16;
    const int m0 = blockIdx.y * 4;
    const int tid = threadIdx.x;

    for (int i = tid; i < 4 * DIM; i += 256)
        msf[i] = mem[(size_t)(m0 + (i >> 10)) * DIM + (i & (DIM - 1))];
    __syncthreads();

    const int col = c0 + (tid & 15);
    const int m   = (tid >> 4) & 3;
    const int eg  = tid >> 6;              // 0..3, each covers 256 e
    const float* mrow = &msf[m * DIM + eg * 256];
    const float* wp = &Wq[(size_t)(eg * 256) * DIM + col];
    float acc = 0.f;
#pragma unroll 8
    for (int i = 0; i < 256; i++)
        acc = fmaf(mrow[i], wp[(size_t)i * DIM], acc);
    red[tid] = acc;
    __syncthreads();
    if (tid < 64) {
        float s = red[tid] + red[tid + 64] + red[tid + 128] + red[tid + 192];
        R[(size_t)(m0 + (tid >> 4)) * DIM + c0 + (tid & 15)] = s;
    }
}

// ---------------- P = mem @ Wf[:,1024:]^T (exact fp32) ------------------------
// grid (64 d-tiles of 16, 16 m-groups of 4). Wf row element reused across 4 m.
__global__ void __launch_bounds__(256) rp_p_kernel(
    const float* __restrict__ mem,         // [64, 1024]
    const float* __restrict__ Wf,          // [1024, 2048]  P[m,d]=sum_c mem[m,c]Wf[d,1024+c]
    float* __restrict__ P)                 // [64, 1024]
{
    __shared__ float msf[4 * DIM];
    const int d0 = blockIdx.x * 16;
    const int m0 = blockIdx.y * 4;
    const int tid = threadIdx.x;

    for (int i = tid; i < 4 * DIM; i += 256)
        msf[i] = mem[(size_t)(m0 + (i >> 10)) * DIM + (i & (DIM - 1))];
    __syncthreads();

    const int d  = d0 + (tid >> 4);
    const int el = tid & 15;
    const float* wrow = &Wf[(size_t)d * (2 * DIM) + DIM];
    float acc0 = 0.f, acc1 = 0.f, acc2 = 0.f, acc3 = 0.f;
#pragma unroll 8
    for (int i = 0; i < 64; i++) {
        int e = el + i * 16;
        float w = wrow[e];
        acc0 = fmaf(msf[e],           w, acc0);
        acc1 = fmaf(msf[DIM + e],     w, acc1);
        acc2 = fmaf(msf[2 * DIM + e], w, acc2);
        acc3 = fmaf(msf[3 * DIM + e], w, acc3);
    }
#pragma unroll
    for (int o = 8; o; o >>= 1) {
        acc0 += __shfl_down_sync(0xffffffffu, acc0, o, 16);
        acc1 += __shfl_down_sync(0xffffffffu, acc1, o, 16);
        acc2 += __shfl_down_sync(0xffffffffu, acc2, o, 16);
        acc3 += __shfl_down_sync(0xffffffffu, acc3, o, 16);
    }
    if (el == 0) {
        P[(size_t)m0 * DIM + d] = acc0;
        P[(size_t)(m0 + 1) * DIM + d] = acc1;
        P[(size_t)(m0 + 2) * DIM + d] = acc2;
        P[(size_t)(m0 + 3) * DIM + d] = acc3;
    }
}

// ---------------- c = mem @ bq ------------------------------------------------
__global__ void __launch_bounds__(256) cvec_kernel(
    const float* __restrict__ mem, const float* __restrict__ bq,
    float* __restrict__ c)
{
    const int warp = threadIdx.x >> 5, lane = threadIdx.x & 31;
    const int m = blockIdx.x * 8 + warp;
    const float4* mr = reinterpret_cast<const float4*>(mem + (size_t)m * DIM);
    const float4* bv = reinterpret_cast<const float4*>(bq);
    float s = 0.f;
#pragma unroll
    for (int i = 0; i < 8; i++) {
        float4 a = mr[lane + i * 32];
        float4 b = bv[lane + i * 32];
        s = fmaf(a.x, b.x, s); s = fmaf(a.y, b.y, s);
        s = fmaf(a.z, b.z, s); s = fmaf(a.w, b.w, s);
    }
#pragma unroll
    for (int o = 16; o; o >>= 1) s += __shfl_xor_sync(0xffffffffu, s, o);
    if (lane == 0) c[m] = s;
}

// ---------------- sim = x @ R^T + c (exact fp32), also emits xh/xl -----------
// block: 64 tokens x 64 slots, K-tiles of 32. 256 threads, 4x4 acc each.
// x is staged through smem exactly once -> fp16 hi/lo split written as byproduct.
#define SIM_TOK 64
__global__ void __launch_bounds__(256) sim_kernel(
    const float* __restrict__ x,           // [16384, 1024]
    const float* __restrict__ R,           // [64, 1024]
    const float* __restrict__ c,           // [64]
    float* __restrict__ sim,               // [16384, 64]
    __half2* __restrict__ xh2,             // [16384, 1024] as half2
    __half2* __restrict__ xl2)
{
    __shared__ float xs[64][33];
    __shared__ float rs[64][33];
    __shared__ float cs[64];

    const int n0 = blockIdx.x * SIM_TOK;
    const int tid = threadIdx.x;
    const int tx = tid & 15;               // m group
    const int ty = tid >> 4;               // token group
    if (tid < 64) cs[tid] = c[tid];

    float acc[4][4];
#pragma unroll
    for (int i = 0; i < 4; i++)
#pragma unroll
        for (int j = 0; j < 4; j++) acc[i][j] = 0.f;

    for (int kt = 0; kt < DIM; kt += 32) {
        __syncthreads();
#pragma unroll
        for (int q = 0; q < 2; q++) {
            int f = tid + q * 256;          // 0..511
            int row = f >> 3;
            int c4 = (f & 7) * 4;
            float4 v = *reinterpret_cast<const float4*>(
                &x[(size_t)(n0 + row) * DIM + kt + c4]);
            xs[row][c4] = v.x; xs[row][c4 + 1] = v.y;
            xs[row][c4 + 2] = v.z; xs[row][c4 + 3] = v.w;
            float4 r = *reinterpret_cast<const float4*>(
                &R[(size_t)row * DIM + kt + c4]);
            rs[row][c4] = r.x; rs[row][c4 + 1] = r.y;
            rs[row][c4 + 2] = r.z; rs[row][c4 + 3] = r.w;
            // fp16 split of x, written once per element across the kernel
            __half hx = __float2half_rn(v.x);
            __half hy = __float2half_rn(v.y);
            __half hz = __float2half_rn(v.z);
            __half hw = __float2half_rn(v.w);
            __half2 h0; h0.x = hx; h0.y = hy;
            __half2 h1; h1.x = hz; h1.y = hw;
            __half2 l0;
            l0.x = __float2half_rn(v.x - __half2float(hx));
            l0.y = __float2half_rn(v.y - __half2float(hy));
            __half2 l1;
            l1.x = __float2half_rn(v.z - __half2float(hz));
            l1.y = __float2half_rn(v.w - __half2float(hw));
            size_t hb = ((size_t)(n0 + row) * DIM + kt + c4) >> 1;
            xh2[hb] = h0; xh2[hb + 1] = h1;
            xl2[hb] = l0; xl2[hb + 1] = l1;
        }
        __syncthreads();
#pragma unroll
        for (int kk = 0; kk < 32; kk++) {
            float a[4], b[4];
#pragma unroll
            for (int i = 0; i < 4; i++) a[i] = xs[ty * 4 + i][kk];
#pragma unroll
            for (int j = 0; j < 4; j++) b[j] = rs[tx * 4 + j][kk];
#pragma unroll
            for (int i = 0; i < 4; i++)
#pragma unroll
                for (int j = 0; j < 4; j++)
                    acc[i][j] = fmaf(a[i], b[j], acc[i][j]);
        }
    }
#pragma unroll
    for (int i = 0; i < 4; i++) {
        float4 o;
        o.x = acc[i][0] + cs[tx * 4 + 0];
        o.y = acc[i][1] + cs[tx * 4 + 1];
        o.z = acc[i][2] + cs[tx * 4 + 2];
        o.w = acc[i][3] + cs[tx * 4 + 3];
        *reinterpret_cast<float4*>(
            &sim[(size_t)(n0 + ty * 4 + i) * MSL + tx * 4]) = o;
    }
}

// ---------------- fp16x2 HMMA GEMM: Hx = x @ Wf_x^T + bf ---------------------
#define GBM 128
#define GBN 128
#define GBK 64
#define TILE_B 16384u
#define OFF_AH 0u
#define OFF_AL (TILE_B)
#define OFF_B  (2u * TILE_B)
#define STAGE_B (3u * TILE_B)
#define NSTAGE 3
#define GEMM_SMEM (NSTAGE * STAGE_B)      // 144 KB

__global__ void __launch_bounds__(256, 1) gemm_fp16x2_kernel(
    const __half* __restrict__ Ah, const __half* __restrict__ Al,
    const __half* __restrict__ B,          // [1024,1024] fp16
    const float* __restrict__ bias,        // [1024]
    float* __restrict__ C)                 // [16384,1024]
{
    extern __shared__ char smem[];
    const uint32_t sb = smem_u32(smem);
    const int tid = threadIdx.x;
    const int wid = tid >> 5;
    const int lane = tid & 31;
    const int n0 = blockIdx.y * GBM;
    const int e0 = blockIdx.x * GBN;
    const int nchunk = DIM / GBK;          // 16

    const uint32_t warp_m = (uint32_t)(wid >> 2) * 64u;
    const uint32_t warp_n = (uint32_t)(wid & 3) * 32u;

    float acc[4][4][4];
#pragma unroll
    for (int mt = 0; mt < 4; mt++)
#pragma unroll
        for (int nt = 0; nt < 4; nt++)
#pragma unroll
            for (int j = 0; j < 4; j++) acc[mt][nt][j] = 0.f;

    auto load_stage = [&](int i, int s) {
        const int kt = i * GBK;
        const uint32_t sbase = sb + (uint32_t)s * STAGE_B;
#pragma unroll
        for (int j = 0; j < 4; j++) {
            int g = tid + j * 256;
            uint32_t r = (uint32_t)(g >> 3);
            uint32_t cc = (uint32_t)(g & 7);
            uint32_t so = sw(r, cc);
            cpasync16(sbase + OFF_AH + so, Ah + (size_t)(n0 + r) * DIM + kt + cc * 8);
            cpasync16(sbase + OFF_AL + so, Al + (size_t)(n0 + r) * DIM + kt + cc * 8);
            cpasync16(sbase + OFF_B  + so, B  + (size_t)(e0 + r) * DIM + kt + cc * 8);
        }
    };

    load_stage(0, 0); cp_commit();
    load_stage(1, 1); cp_commit();

    for (int i = 0; i < nchunk; i++) {
        cp_wait1();
        __syncthreads();
        if (i + 2 < nchunk) load_stage(i + 2, (i + 2) % NSTAGE);
        cp_commit();

        const uint32_t base = sb + (uint32_t)(i % NSTAGE) * STAGE_B;
#pragma unroll
        for (int k16 = 0; k16 < 4; k16++) {
            uint32_t ah[4][4], al[4][4];
            const uint32_t arow = (uint32_t)(lane & 15);
            const uint32_t acnk = (uint32_t)(2 * k16 + (lane >> 4));
#pragma unroll
            for (int mt = 0; mt < 4; mt++) {
                uint32_t so = sw(warp_m + (uint32_t)mt * 16u + arow, acnk);
                ldsm4(ah[mt], base + OFF_AH + so);
                ldsm4(al[mt], base + OFF_AL + so);
            }
            uint32_t bf[4][2];
            const uint32_t brow0 = (uint32_t)((lane & 7) + ((lane >> 4) & 1) * 8);
            const uint32_t bcnk  = (uint32_t)(2 * k16 + ((lane >> 3) & 1));
#pragma unroll
            for (int half = 0; half < 2; half++) {
                uint32_t so = sw(warp_n + (uint32_t)half * 16u + brow0, bcnk);
                uint32_t t[4];
                ldsm4(t, base + OFF_B + so);
                bf[2 * half][0] = t[0];     bf[2 * half][1] = t[1];
                bf[2 * half + 1][0] = t[2]; bf[2 * half + 1][1] = t[3];
            }
#pragma unroll
            for (int mt = 0; mt < 4; mt++) {
#pragma unroll
                for (int nt = 0; nt < 4; nt++) {
                    mma16816(acc[mt][nt], ah[mt], bf[nt][0], bf[nt][1]);
                    mma16816(acc[mt][nt], al[mt], bf[nt][0], bf[nt][1]);
                }
            }
        }
    }

#pragma unroll
    for (int mt = 0; mt < 4; mt++) {
#pragma unroll
        for (int nt = 0; nt < 4; nt++) {
            int row = n0 + (int)warp_m + mt * 16 + (lane >> 2);
            int col = e0 + (int)warp_n + nt * 8 + (lane & 3) * 2;
            float b0 = bias[col], b1 = bias[col + 1];
            float2 v0; v0.x = acc[mt][nt][0] + b0; v0.y = acc[mt][nt][1] + b1;
            float2 v1; v1.x = acc[mt][nt][2] + b0; v1.y = acc[mt][nt][3] + b1;
            *reinterpret_cast<float2*>(&C[(size_t)row * DIM + col]) = v0;
            *reinterpret_cast<float2*>(&C[(size_t)(row + 8) * DIM + col]) = v1;
        }
    }
}

// ---------------- tail: top3(sim) -> H = Hx + sum w P -> LN -> ReLU -----------
__global__ void __launch_bounds__(256) tail_kernel(
    const float* __restrict__ sim,         // [16384, 64]
    const float* __restrict__ Hx,          // [16384, 1024]
    const float* __restrict__ P,           // [64, 1024]
    const float* __restrict__ gamma,
    const float* __restrict__ beta,
    float* __restrict__ out)
{
    const int n = blockIdx.x;
    const int tid = threadIdx.x;
    const int lane = tid & 31;
    const int warp = tid >> 5;

    __shared__ float sim_s[MSL];
    __shared__ float wgt[KTOP];
    __shared__ int   sidx[KTOP];
    __shared__ float sh_s[8], sh_ss[8];

    if (tid < MSL) sim_s[tid] = sim[(size_t)n * MSL + tid];
    __syncthreads();

    if (tid == 0) {
        float v0 = -3.4e38f, v1 = -3.4e38f, v2 = -3.4e38f;
        int i0 = 0, i1 = 0, i2 = 0;
        for (int m = 0; m < MSL; m++) {
            float v = sim_s[m];
            if (v > v0)      { v2 = v1; i2 = i1; v1 = v0; i1 = i0; v0 = v; i0 = m; }
            else if (v > v1) { v2 = v1; i2 = i1; v1 = v;  i1 = m; }
            else if (v > v2) { v2 = v;  i2 = m; }
        }
        float e1 = __expf(v1 - v0);
        float e2 = __expf(v2 - v0);
        float inv = 1.f / (1.f + e1 + e2);
        wgt[0] = inv; wgt[1] = e1 * inv; wgt[2] = e2 * inv;
        sidx[0] = i0; sidx[1] = i1; sidx[2] = i2;
    }
    __syncthreads();

    const float w0 = wgt[0], w1 = wgt[1], w2 = wgt[2];
    float4 v  = reinterpret_cast<const float4*>(Hx + (size_t)n * DIM)[tid];
    float4 p0 = reinterpret_cast<const float4*>(P + (size_t)sidx[0] * DIM)[tid];
    float4 p1 = reinterpret_cast<const float4*>(P + (size_t)sidx[1] * DIM)[tid];
    float4 p2 = reinterpret_cast<const float4*>(P + (size_t)sidx[2] * DIM)[tid];
    v.x += w0 * p0.x + w1 * p1.x + w2 * p2.x;
    v.y += w0 * p0.y + w1 * p1.y + w2 * p2.y;
    v.z += w0 * p0.z + w1 * p1.z + w2 * p2.z;
    v.w += w0 * p0.w + w1 * p1.w + w2 * p2.w;

    float s  = v.x + v.y + v.z + v.w;
    float ss = v.x * v.x + v.y * v.y + v.z * v.z + v.w * v.w;
#pragma unroll
    for (int o = 16; o; o >>= 1) {
        s  += __shfl_xor_sync(0xffffffffu, s, o);
        ss += __shfl_xor_sync(0xffffffffu, ss, o);
    }
    if (lane == 0) { sh_s[warp] = s; sh_ss[warp] = ss; }
    __syncthreads();
    if (warp == 0) {
        s  = (lane < 8) ? sh_s[lane]  : 0.f;
        ss = (lane < 8) ? sh_ss[lane] : 0.f;
#pragma unroll
        for (int o = 4; o; o >>= 1) {
            s  += __shfl_xor_sync(0xffffffffu, s, o);
            ss += __shfl_xor_sync(0xffffffffu, ss, o);
        }
        if (lane == 0) { sh_s[0] = s; sh_ss[0] = ss; }
    }
    __syncthreads();

    const float mean = sh_s[0] * (1.f / DIM);
    const float var  = sh_ss[0] * (1.f / DIM) - mean * mean;
    const float rstd = rsqrtf(var + LN_EPS);
    float4 g = reinterpret_cast<const float4*>(gamma)[tid];
    float4 bb = reinterpret_cast<const float4*>(beta)[tid];
    float4 o;
    o.x = fmaxf((v.x - mean) * rstd * g.x + bb.x, 0.f);
    o.y = fmaxf((v.y - mean) * rstd * g.y + bb.y, 0.f);
    o.z = fmaxf((v.z - mean) * rstd * g.z + bb.z, 0.f);
    o.w = fmaxf((v.w - mean) * rstd * g.w + bb.w, 0.f);
    reinterpret_cast<float4*>(out + (size_t)n * DIM)[tid] = o;
}

// ---------------- host --------------------------------------------------------
extern "C" void kernel_launch(void* const* d_in, const int* in_sizes, int n_in,
                              void* d_out, int out_size)
{
    const float* x      = (const float*)d_in[0];
    const float* memory = (const float*)d_in[1];
    const float* Wq     = (const float*)d_in[2];
    const float* bq     = (const float*)d_in[3];
    const float* Wf     = (const float*)d_in[4];
    const float* bf     = (const float*)d_in[5];
    const float* gamma  = (const float*)d_in[6];
    const float* beta   = (const float*)d_in[7];
    float* out = (float*)d_out;

    void *xh, *xl, *wfx, *R, *c, *P, *sim, *Hx;
    cudaGetSymbolAddress(&xh,  g_xh);  cudaGetSymbolAddress(&xl, g_xl);
    cudaGetSymbolAddress(&wfx, g_wfx); cudaGetSymbolAddress(&R,  g_R);
    cudaGetSymbolAddress(&c,   g_c);   cudaGetSymbolAddress(&P,  g_P);
    cudaGetSymbolAddress(&sim, g_sim); cudaGetSymbolAddress(&Hx, g_Hx);

    static bool attr_set = false;
    if (!attr_set) {
        cudaFuncSetAttribute(gemm_fp16x2_kernel,
                             cudaFuncAttributeMaxDynamicSharedMemorySize, GEMM_SMEM);
        attr_set = true;
    }

    // 1) exact precomputes (well-parallelized) + weight pack
    pack_wfx_kernel<<<DIM * DIM / 4 / 256, 256>>>(Wf, (__half2*)wfx);
    rp_r_kernel<<<dim3(64, 16), 256>>>(memory, Wq, (float*)R);
    rp_p_kernel<<<dim3(64, 16), 256>>>(memory, Wf, (float*)P);
    cvec_kernel<<<8, 256>>>(memory, bq, (float*)c);

    // 2) sim = x @ R^T + c (exact fp32); also emits xh/xl fp16 split
    sim_kernel<<<NTOK / SIM_TOK, 256>>>(x, (const float*)R, (const float*)c,
                                        (float*)sim, (__half2*)xh, (__half2*)xl);

    // 3) Hx = x @ Wf_x^T + bf  (fp16 split tensor-core GEMM)
    dim3 gg(DIM / GBN, NTOK / GBM);   // (8, 128)
    gemm_fp16x2_kernel<<<gg, 256, GEMM_SMEM>>>(
        (const __half*)xh, (const __half*)xl,
        (const __half*)wfx, bf, (float*)Hx);

    // 4) tail: top3/softmax + P gather + LN + ReLU
    tail_kernel<<<NTOK, 256>>>((const float*)sim, (const float*)Hx,
                               (const float*)P, gamma, beta, out);
}

// round 8
// speedup vs baseline: 7.1177x; 1.0175x over previous
#include <cuda_runtime.h>
#include <cuda_fp16.h>
#include <math.h>
#include <stdint.h>

#define NTOK (8 * 2048)      // 16384 rows
#define DIM  1024
#define MSL  64
#define KTOP 3
#define LN_EPS 1e-5f

// ---------------- scratch (allocation-free rule: __device__ globals) -------
__device__ __half g_xh[(size_t)NTOK * DIM];
__device__ __half g_xl[(size_t)NTOK * DIM];
__device__ __half g_wfx[(size_t)DIM * DIM];       // Wf[:, :1024] fp16
__device__ float g_R[(size_t)MSL * DIM];          // mem @ Wq       (exact fp32)
__device__ float g_c[MSL];                        // mem @ bq
__device__ float g_P[(size_t)MSL * DIM];          // mem @ Wf_m^T   (exact fp32)
__device__ float g_sim[(size_t)NTOK * MSL];       // similarity scores
__device__ float g_Hx[(size_t)NTOK * DIM];        // x @ Wf_x^T + bf

// ---------------- helpers ----------------------------------------------------
__device__ __forceinline__ uint32_t smem_u32(const void* p) {
    uint32_t a;
    asm("{ .reg .u64 t; cvta.to.shared.u64 t, %1; cvt.u32.u64 %0, t; }" : "=r"(a) : "l"(p));
    return a;
}
__device__ __forceinline__ void cpasync16(uint32_t s, const void* g) {
    asm volatile("cp.async.cg.shared.global [%0], [%1], 16;" :: "r"(s), "l"(g));
}
__device__ __forceinline__ void cp_commit() {
    asm volatile("cp.async.commit_group;");
}
__device__ __forceinline__ void cp_wait2() {
    asm volatile("cp.async.wait_group 2;");
}
__device__ __forceinline__ void ldsm4(uint32_t* t, uint32_t addr) {
    asm volatile("ldmatrix.sync.aligned.m8n8.x4.shared.b16 {%0,%1,%2,%3}, [%4];"
        : "=r"(t[0]), "=r"(t[1]), "=r"(t[2]), "=r"(t[3]) : "r"(addr));
}
__device__ __forceinline__ void mma16816(float* d, const uint32_t* a,
                                         uint32_t b0, uint32_t b1) {
    asm volatile(
        "mma.sync.aligned.m16n8k16.row.col.f32.f16.f16.f32 "
        "{%0,%1,%2,%3}, {%4,%5,%6,%7}, {%8,%9}, {%0,%1,%2,%3};"
        : "+f"(d[0]), "+f"(d[1]), "+f"(d[2]), "+f"(d[3])
        : "r"(a[0]), "r"(a[1]), "r"(a[2]), "r"(a[3]), "r"(b0), "r"(b1));
}
// XOR swizzle: 128-row x 64-col fp16 tile, 16B chunks (8/row), pitch 128B.
__device__ __forceinline__ uint32_t sw(uint32_t row, uint32_t c) {
    return row * 128u + ((c ^ (row & 7u)) << 4);
}

// ---------------- split fp32 -> (fp16 hi, fp16 lo) ---------------------------
__global__ void __launch_bounds__(256) split_kernel(
    const float4* __restrict__ in, __half2* __restrict__ hi,
    __half2* __restrict__ lo, int n4)
{
    int i = blockIdx.x * 256 + threadIdx.x;
    if (i >= n4) return;
    float4 v = in[i];
    __half hx = __float2half_rn(v.x);
    __half hy = __float2half_rn(v.y);
    __half hz = __float2half_rn(v.z);
    __half hw = __float2half_rn(v.w);
    __half2 h0; h0.x = hx; h0.y = hy;
    __half2 h1; h1.x = hz; h1.y = hw;
    __half2 l0;
    l0.x = __float2half_rn(v.x - __half2float(hx));
    l0.y = __float2half_rn(v.y - __half2float(hy));
    __half2 l1;
    l1.x = __float2half_rn(v.z - __half2float(hz));
    l1.y = __float2half_rn(v.w - __half2float(hw));
    hi[2 * i] = h0; hi[2 * i + 1] = h1;
    lo[2 * i] = l0; lo[2 * i + 1] = l1;
}

// ---------------- pack Wf[:, :1024] -> fp16 -----------------------------------
__global__ void __launch_bounds__(256) pack_wfx_kernel(
    const float* __restrict__ Wf,          // [1024, 2048]
    __half2* __restrict__ wfx)             // [1024, 1024] fp16
{
    int i4 = blockIdx.x * 256 + threadIdx.x;      // float4 idx over 1024x1024
    if (i4 >= DIM * DIM / 4) return;
    int d = i4 >> 8;
    int c = (i4 & 255) * 4;
    float4 v = *reinterpret_cast<const float4*>(&Wf[(size_t)d * (2 * DIM) + c]);
    __half2 a; a.x = __float2half_rn(v.x); a.y = __float2half_rn(v.y);
    __half2 b; b.x = __float2half_rn(v.z); b.y = __float2half_rn(v.w);
    wfx[2 * i4] = a; wfx[2 * i4 + 1] = b;
}

// ---------------- R = mem @ Wq (exact fp32) -----------------------------------
__global__ void __launch_bounds__(256) rp_r_kernel(
    const float* __restrict__ mem,         // [64, 1024]
    const float* __restrict__ Wq,          // [1024, 1024]  R[m,d]=sum_e mem[m,e]Wq[e,d]
    float* __restrict__ R)                 // [64, 1024]
{
    __shared__ float msf[4 * DIM];
    __shared__ float red[256];
    const int c0 = blockIdx.x * 16;
    const int m0 = blockIdx.y * 4;
    const int tid = threadIdx.x;

    for (int i = tid; i < 4 * DIM; i += 256)
        msf[i] = mem[(size_t)(m0 + (i >> 10)) * DIM + (i & (DIM - 1))];
    __syncthreads();

    const int col = c0 + (tid & 15);
    const int m   = (tid >> 4) & 3;
    const int eg  = tid >> 6;
    const float* mrow = &msf[m * DIM + eg * 256];
    const float* wp = &Wq[(size_t)(eg * 256) * DIM + col];
    float acc = 0.f;
#pragma unroll 8
    for (int i = 0; i < 256; i++)
        acc = fmaf(mrow[i], wp[(size_t)i * DIM], acc);
    red[tid] = acc;
    __syncthreads();
    if (tid < 64) {
        float s = red[tid] + red[tid + 64] + red[tid + 128] + red[tid + 192];
        R[(size_t)(m0 + (tid >> 4)) * DIM + c0 + (tid & 15)] = s;
    }
}

// ---------------- P = mem @ Wf[:,1024:]^T (exact fp32) ------------------------
__global__ void __launch_bounds__(256) rp_p_kernel(
    const float* __restrict__ mem,
    const float* __restrict__ Wf,
    float* __restrict__ P)
{
    __shared__ float msf[4 * DIM];
    const int d0 = blockIdx.x * 16;
    const int m0 = blockIdx.y * 4;
    const int tid = threadIdx.x;

    for (int i = tid; i < 4 * DIM; i += 256)
        msf[i] = mem[(size_t)(m0 + (i >> 10)) * DIM + (i & (DIM - 1))];
    __syncthreads();

    const int d  = d0 + (tid >> 4);
    const int el = tid & 15;
    const float* wrow = &Wf[(size_t)d * (2 * DIM) + DIM];
    float acc0 = 0.f, acc1 = 0.f, acc2 = 0.f, acc3 = 0.f;
#pragma unroll 8
    for (int i = 0; i < 64; i++) {
        int e = el + i * 16;
        float w = wrow[e];
        acc0 = fmaf(msf[e],           w, acc0);
        acc1 = fmaf(msf[DIM + e],     w, acc1);
        acc2 = fmaf(msf[2 * DIM + e], w, acc2);
        acc3 = fmaf(msf[3 * DIM + e], w, acc3);
    }
#pragma unroll
    for (int o = 8; o; o >>= 1) {
        acc0 += __shfl_down_sync(0xffffffffu, acc0, o, 16);
        acc1 += __shfl_down_sync(0xffffffffu, acc1, o, 16);
        acc2 += __shfl_down_sync(0xffffffffu, acc2, o, 16);
        acc3 += __shfl_down_sync(0xffffffffu, acc3, o, 16);
    }
    if (el == 0) {
        P[(size_t)m0 * DIM + d] = acc0;
        P[(size_t)(m0 + 1) * DIM + d] = acc1;
        P[(size_t)(m0 + 2) * DIM + d] = acc2;
        P[(size_t)(m0 + 3) * DIM + d] = acc3;
    }
}

// ---------------- c = mem @ bq ------------------------------------------------
__global__ void __launch_bounds__(256) cvec_kernel(
    const float* __restrict__ mem, const float* __restrict__ bq,
    float* __restrict__ c)
{
    const int warp = threadIdx.x >> 5, lane = threadIdx.x & 31;
    const int m = blockIdx.x * 8 + warp;
    const float4* mr = reinterpret_cast<const float4*>(mem + (size_t)m * DIM);
    const float4* bv = reinterpret_cast<const float4*>(bq);
    float s = 0.f;
#pragma unroll
    for (int i = 0; i < 8; i++) {
        float4 a = mr[lane + i * 32];
        float4 b = bv[lane + i * 32];
        s = fmaf(a.x, b.x, s); s = fmaf(a.y, b.y, s);
        s = fmaf(a.z, b.z, s); s = fmaf(a.w, b.w, s);
    }
#pragma unroll
    for (int o = 16; o; o >>= 1) s += __shfl_xor_sync(0xffffffffu, s, o);
    if (lane == 0) c[m] = s;
}

// ---------------- sim = x @ R^T + c (exact fp32) ------------------------------
#define SIM_TOK 64
__global__ void __launch_bounds__(256) sim_kernel(
    const float* __restrict__ x,
    const float* __restrict__ R,
    const float* __restrict__ c,
    float* __restrict__ sim)
{
    __shared__ float xs[64][33];
    __shared__ float rs[64][33];
    __shared__ float cs[64];

    const int n0 = blockIdx.x * SIM_TOK;
    const int tid = threadIdx.x;
    const int tx = tid & 15;
    const int ty = tid >> 4;
    if (tid < 64) cs[tid] = c[tid];

    float acc[4][4];
#pragma unroll
    for (int i = 0; i < 4; i++)
#pragma unroll
        for (int j = 0; j < 4; j++) acc[i][j] = 0.f;

    for (int kt = 0; kt < DIM; kt += 32) {
        __syncthreads();
#pragma unroll
        for (int q = 0; q < 2; q++) {
            int f = tid + q * 256;
            int row = f >> 3;
            int c4 = (f & 7) * 4;
            float4 v = *reinterpret_cast<const float4*>(
                &x[(size_t)(n0 + row) * DIM + kt + c4]);
            xs[row][c4] = v.x; xs[row][c4 + 1] = v.y;
            xs[row][c4 + 2] = v.z; xs[row][c4 + 3] = v.w;
            float4 r = *reinterpret_cast<const float4*>(
                &R[(size_t)row * DIM + kt + c4]);
            rs[row][c4] = r.x; rs[row][c4 + 1] = r.y;
            rs[row][c4 + 2] = r.z; rs[row][c4 + 3] = r.w;
        }
        __syncthreads();
#pragma unroll
        for (int kk = 0; kk < 32; kk++) {
            float a[4], b[4];
#pragma unroll
            for (int i = 0; i < 4; i++) a[i] = xs[ty * 4 + i][kk];
#pragma unroll
            for (int j = 0; j < 4; j++) b[j] = rs[tx * 4 + j][kk];
#pragma unroll
            for (int i = 0; i < 4; i++)
#pragma unroll
                for (int j = 0; j < 4; j++)
                    acc[i][j] = fmaf(a[i], b[j], acc[i][j]);
        }
    }
#pragma unroll
    for (int i = 0; i < 4; i++) {
        float4 o;
        o.x = acc[i][0] + cs[tx * 4 + 0];
        o.y = acc[i][1] + cs[tx * 4 + 1];
        o.z = acc[i][2] + cs[tx * 4 + 2];
        o.w = acc[i][3] + cs[tx * 4 + 3];
        *reinterpret_cast<float4*>(
            &sim[(size_t)(n0 + ty * 4 + i) * MSL + tx * 4]) = o;
    }
}

// ---------------- fp16x2 HMMA GEMM: Hx = x @ Wf_x^T + bf ---------------------
// 4-stage cp.async ring, wait_group 2 (two chunks in flight).
#define GBM 128
#define GBN 128
#define GBK 64
#define TILE_B 16384u
#define OFF_AH 0u
#define OFF_AL (TILE_B)
#define OFF_B  (2u * TILE_B)
#define STAGE_B (3u * TILE_B)             // 48 KB
#define NSTAGE 4
#define GEMM_SMEM (NSTAGE * STAGE_B)      // 192 KB

__global__ void __launch_bounds__(256, 1) gemm_fp16x2_kernel(
    const __half* __restrict__ Ah, const __half* __restrict__ Al,
    const __half* __restrict__ B,
    const float* __restrict__ bias,
    float* __restrict__ C)
{
    extern __shared__ char smem[];
    const uint32_t sb = smem_u32(smem);
    const int tid = threadIdx.x;
    const int wid = tid >> 5;
    const int lane = tid & 31;
    const int n0 = blockIdx.y * GBM;
    const int e0 = blockIdx.x * GBN;
    const int nchunk = DIM / GBK;          // 16

    const uint32_t warp_m = (uint32_t)(wid >> 2) * 64u;
    const uint32_t warp_n = (uint32_t)(wid & 3) * 32u;

    float acc[4][4][4];
#pragma unroll
    for (int mt = 0; mt < 4; mt++)
#pragma unroll
        for (int nt = 0; nt < 4; nt++)
#pragma unroll
            for (int j = 0; j < 4; j++) acc[mt][nt][j] = 0.f;

    auto load_stage = [&](int i, int s) {
        const int kt = i * GBK;
        const uint32_t sbase = sb + (uint32_t)s * STAGE_B;
#pragma unroll
        for (int j = 0; j < 4; j++) {
            int g = tid + j * 256;
            uint32_t r = (uint32_t)(g >> 3);
            uint32_t cc = (uint32_t)(g & 7);
            uint32_t so = sw(r, cc);
            cpasync16(sbase + OFF_AH + so, Ah + (size_t)(n0 + r) * DIM + kt + cc * 8);
            cpasync16(sbase + OFF_AL + so, Al + (size_t)(n0 + r) * DIM + kt + cc * 8);
            cpasync16(sbase + OFF_B  + so, B  + (size_t)(e0 + r) * DIM + kt + cc * 8);
        }
    };

    load_stage(0, 0); cp_commit();
    load_stage(1, 1); cp_commit();
    load_stage(2, 2); cp_commit();

    for (int i = 0; i < nchunk; i++) {
        cp_wait2();                 // stage i complete
        __syncthreads();            // all warps done with stage (i+3)%4
        if (i + 3 < nchunk) load_stage(i + 3, (i + 3) & 3);
        cp_commit();

        const uint32_t base = sb + (uint32_t)(i & 3) * STAGE_B;
#pragma unroll
        for (int k16 = 0; k16 < 4; k16++) {
            uint32_t ah[4][4], al[4][4];
            const uint32_t arow = (uint32_t)(lane & 15);
            const uint32_t acnk = (uint32_t)(2 * k16 + (lane >> 4));
#pragma unroll
            for (int mt = 0; mt < 4; mt++) {
                uint32_t so = sw(warp_m + (uint32_t)mt * 16u + arow, acnk);
                ldsm4(ah[mt], base + OFF_AH + so);
                ldsm4(al[mt], base + OFF_AL + so);
            }
            uint32_t bf[4][2];
            const uint32_t brow0 = (uint32_t)((lane & 7) + ((lane >> 4) & 1) * 8);
            const uint32_t bcnk  = (uint32_t)(2 * k16 + ((lane >> 3) & 1));
#pragma unroll
            for (int half = 0; half < 2; half++) {
                uint32_t so = sw(warp_n + (uint32_t)half * 16u + brow0, bcnk);
                uint32_t t[4];
                ldsm4(t, base + OFF_B + so);
                bf[2 * half][0] = t[0];     bf[2 * half][1] = t[1];
                bf[2 * half + 1][0] = t[2]; bf[2 * half + 1][1] = t[3];
            }
#pragma unroll
            for (int mt = 0; mt < 4; mt++) {
#pragma unroll
                for (int nt = 0; nt < 4; nt++) {
                    mma16816(acc[mt][nt], ah[mt], bf[nt][0], bf[nt][1]);
                    mma16816(acc[mt][nt], al[mt], bf[nt][0], bf[nt][1]);
                }
            }
        }
    }

#pragma unroll
    for (int mt = 0; mt < 4; mt++) {
#pragma unroll
        for (int nt = 0; nt < 4; nt++) {
            int row = n0 + (int)warp_m + mt * 16 + (lane >> 2);
            int col = e0 + (int)warp_n + nt * 8 + (lane & 3) * 2;
            float b0 = bias[col], b1 = bias[col + 1];
            float2 v0; v0.x = acc[mt][nt][0] + b0; v0.y = acc[mt][nt][1] + b1;
            float2 v1; v1.x = acc[mt][nt][2] + b0; v1.y = acc[mt][nt][3] + b1;
            *reinterpret_cast<float2*>(&C[(size_t)row * DIM + col]) = v0;
            *reinterpret_cast<float2*>(&C[(size_t)(row + 8) * DIM + col]) = v1;
        }
    }
}

// ---------------- tail: top3(sim) -> H = Hx + sum w P -> LN -> ReLU -----------
__global__ void __launch_bounds__(256) tail_kernel(
    const float* __restrict__ sim,
    const float* __restrict__ Hx,
    const float* __restrict__ P,
    const float* __restrict__ gamma,
    const float* __restrict__ beta,
    float* __restrict__ out)
{
    const int n = blockIdx.x;
    const int tid = threadIdx.x;
    const int lane = tid & 31;
    const int warp = tid >> 5;

    __shared__ float sim_s[MSL];
    __shared__ float wgt[KTOP];
    __shared__ int   sidx[KTOP];
    __shared__ float sh_s[8], sh_ss[8];

    if (tid < MSL) sim_s[tid] = sim[(size_t)n * MSL + tid];
    __syncthreads();

    if (tid == 0) {
        float v0 = -3.4e38f, v1 = -3.4e38f, v2 = -3.4e38f;
        int i0 = 0, i1 = 0, i2 = 0;
        for (int m = 0; m < MSL; m++) {
            float v = sim_s[m];
            if (v > v0)      { v2 = v1; i2 = i1; v1 = v0; i1 = i0; v0 = v; i0 = m; }
            else if (v > v1) { v2 = v1; i2 = i1; v1 = v;  i1 = m; }
            else if (v > v2) { v2 = v;  i2 = m; }
        }
        float e1 = __expf(v1 - v0);
        float e2 = __expf(v2 - v0);
        float inv = 1.f / (1.f + e1 + e2);
        wgt[0] = inv; wgt[1] = e1 * inv; wgt[2] = e2 * inv;
        sidx[0] = i0; sidx[1] = i1; sidx[2] = i2;
    }
    __syncthreads();

    const float w0 = wgt[0], w1 = wgt[1], w2 = wgt[2];
    float4 v  = reinterpret_cast<const float4*>(Hx + (size_t)n * DIM)[tid];
    float4 p0 = reinterpret_cast<const float4*>(P + (size_t)sidx[0] * DIM)[tid];
    float4 p1 = reinterpret_cast<const float4*>(P + (size_t)sidx[1] * DIM)[tid];
    float4 p2 = reinterpret_cast<const float4*>(P + (size_t)sidx[2] * DIM)[tid];
    v.x += w0 * p0.x + w1 * p1.x + w2 * p2.x;
    v.y += w0 * p0.y + w1 * p1.y + w2 * p2.y;
    v.z += w0 * p0.z + w1 * p1.z + w2 * p2.z;
    v.w += w0 * p0.w + w1 * p1.w + w2 * p2.w;

    float s  = v.x + v.y + v.z + v.w;
    float ss = v.x * v.x + v.y * v.y + v.z * v.z + v.w * v.w;
#pragma unroll
    for (int o = 16; o; o >>= 1) {
        s  += __shfl_xor_sync(0xffffffffu, s, o);
        ss += __shfl_xor_sync(0xffffffffu, ss, o);
    }
    if (lane == 0) { sh_s[warp] = s; sh_ss[warp] = ss; }
    __syncthreads();
    if (warp == 0) {
        s  = (lane < 8) ? sh_s[lane]  : 0.f;
        ss = (lane < 8) ? sh_ss[lane] : 0.f;
#pragma unroll
        for (int o = 4; o; o >>= 1) {
            s  += __shfl_xor_sync(0xffffffffu, s, o);
            ss += __shfl_xor_sync(0xffffffffu, ss, o);
        }
        if (lane == 0) { sh_s[0] = s; sh_ss[0] = ss; }
    }
    __syncthreads();

    const float mean = sh_s[0] * (1.f / DIM);
    const float var  = sh_ss[0] * (1.f / DIM) - mean * mean;
    const float rstd = rsqrtf(var + LN_EPS);
    float4 g = reinterpret_cast<const float4*>(gamma)[tid];
    float4 bb = reinterpret_cast<const float4*>(beta)[tid];
    float4 o;
    o.x = fmaxf((v.x - mean) * rstd * g.x + bb.x, 0.f);
    o.y = fmaxf((v.y - mean) * rstd * g.y + bb.y, 0.f);
    o.z = fmaxf((v.z - mean) * rstd * g.z + bb.z, 0.f);
    o.w = fmaxf((v.w - mean) * rstd * g.w + bb.w, 0.f);
    reinterpret_cast<float4*>(out + (size_t)n * DIM)[tid] = o;
}

// ---------------- host --------------------------------------------------------
extern "C" void kernel_launch(void* const* d_in, const int* in_sizes, int n_in,
                              void* d_out, int out_size)
{
    const float* x      = (const float*)d_in[0];
    const float* memory = (const float*)d_in[1];
    const float* Wq     = (const float*)d_in[2];
    const float* bq     = (const float*)d_in[3];
    const float* Wf     = (const float*)d_in[4];
    const float* bf     = (const float*)d_in[5];
    const float* gamma  = (const float*)d_in[6];
    const float* beta   = (const float*)d_in[7];
    float* out = (float*)d_out;

    void *xh, *xl, *wfx, *R, *c, *P, *sim, *Hx;
    cudaGetSymbolAddress(&xh,  g_xh);  cudaGetSymbolAddress(&xl, g_xl);
    cudaGetSymbolAddress(&wfx, g_wfx); cudaGetSymbolAddress(&R,  g_R);
    cudaGetSymbolAddress(&c,   g_c);   cudaGetSymbolAddress(&P,  g_P);
    cudaGetSymbolAddress(&sim, g_sim); cudaGetSymbolAddress(&Hx, g_Hx);

    static cudaStream_t s1 = nullptr, s2 = nullptr;
    static cudaEvent_t evRoot = nullptr, evPack = nullptr, evSim = nullptr, evP = nullptr;
    static bool init_done = false;
    if (!init_done) {
        cudaFuncSetAttribute(gemm_fp16x2_kernel,
                             cudaFuncAttributeMaxDynamicSharedMemorySize, GEMM_SMEM);
        cudaStreamCreateWithFlags(&s1, cudaStreamNonBlocking);
        cudaStreamCreateWithFlags(&s2, cudaStreamNonBlocking);
        cudaEventCreateWithFlags(&evRoot, cudaEventDisableTiming);
        cudaEventCreateWithFlags(&evPack, cudaEventDisableTiming);
        cudaEventCreateWithFlags(&evSim,  cudaEventDisableTiming);
        cudaEventCreateWithFlags(&evP,    cudaEventDisableTiming);
        init_done = true;
    }

    // ---- fork side branches off the (captured) legacy stream ----
    cudaEventRecord(evRoot, 0);
    cudaStreamWaitEvent(s1, evRoot, 0);
    cudaStreamWaitEvent(s2, evRoot, 0);

    // branch B (s1): R, c, then sim
    rp_r_kernel<<<dim3(64, 16), 256, 0, s1>>>(memory, Wq, (float*)R);
    cvec_kernel<<<8, 256, 0, s1>>>(memory, bq, (float*)c);
    sim_kernel<<<NTOK / SIM_TOK, 256, 0, s1>>>(x, (const float*)R,
                                               (const float*)c, (float*)sim);
    cudaEventRecord(evSim, s1);

    // branch C (s2): weight pack (needed by GEMM), then P
    pack_wfx_kernel<<<DIM * DIM / 4 / 256, 256, 0, s2>>>(Wf, (__half2*)wfx);
    cudaEventRecord(evPack, s2);
    rp_p_kernel<<<dim3(64, 16), 256, 0, s2>>>(memory, Wf, (float*)P);
    cudaEventRecord(evP, s2);

    // branch A (stream 0): x split -> GEMM (waits on pack)
    split_kernel<<<NTOK * DIM / 4 / 256, 256>>>(
        (const float4*)x, (__half2*)xh, (__half2*)xl, NTOK * DIM / 4);
    cudaStreamWaitEvent(0, evPack, 0);
    dim3 gg(DIM / GBN, NTOK / GBM);   // (8, 128)
    gemm_fp16x2_kernel<<<gg, 256, GEMM_SMEM>>>(
        (const __half*)xh, (const __half*)xl,
        (const __half*)wfx, bf, (float*)Hx);

    // ---- join: tail needs sim, Hx, P ----
    cudaStreamWaitEvent(0, evSim, 0);
    cudaStreamWaitEvent(0, evP, 0);
    tail_kernel<<<NTOK, 256>>>((const float*)sim, (const float*)Hx,
                               (const float*)P, gamma, beta, out);
}

// round 9
// speedup vs baseline: 7.8490x; 1.1027x over previous
#include <cuda_runtime.h>
#include <cuda_fp16.h>
#include <math.h>
#include <stdint.h>

#define NTOK (8 * 2048)      // 16384 rows
#define DIM  1024
#define NW   1152            // GEMM output width: 1024 Hx | 64 simH | 64 simL
#define MSL  64
#define KTOP 3
#define LN_EPS 1e-5f

// ---------------- scratch (allocation-free rule: __device__ globals) -------
__device__ __half g_xh[(size_t)NTOK * DIM];
__device__ __half g_xl[(size_t)NTOK * DIM];
__device__ __half g_B[(size_t)NW * DIM];          // [Wf_x ; Rh ; Rl] fp16
__device__ float g_bias[NW];                      // [bf | 0...]
__device__ float g_R[(size_t)MSL * DIM];          // mem @ Wq     (exact fp32)
__device__ float g_c[MSL];                        // mem @ bq
__device__ float g_P[(size_t)MSL * DIM];          // mem @ Wf_m^T (exact fp32)
__device__ float g_C[(size_t)NTOK * NW];          // GEMM out

// ---------------- helpers ----------------------------------------------------
__device__ __forceinline__ uint32_t smem_u32(const void* p) {
    uint32_t a;
    asm("{ .reg .u64 t; cvta.to.shared.u64 t, %1; cvt.u32.u64 %0, t; }" : "=r"(a) : "l"(p));
    return a;
}
__device__ __forceinline__ void cpasync16(uint32_t s, const void* g) {
    asm volatile("cp.async.cg.shared.global [%0], [%1], 16;" :: "r"(s), "l"(g));
}
__device__ __forceinline__ void cp_commit() {
    asm volatile("cp.async.commit_group;");
}
__device__ __forceinline__ void cp_wait2() {
    asm volatile("cp.async.wait_group 2;");
}
__device__ __forceinline__ void ldsm4(uint32_t* t, uint32_t addr) {
    asm volatile("ldmatrix.sync.aligned.m8n8.x4.shared.b16 {%0,%1,%2,%3}, [%4];"
        : "=r"(t[0]), "=r"(t[1]), "=r"(t[2]), "=r"(t[3]) : "r"(addr));
}
__device__ __forceinline__ void mma16816(float* d, const uint32_t* a,
                                         uint32_t b0, uint32_t b1) {
    asm volatile(
        "mma.sync.aligned.m16n8k16.row.col.f32.f16.f16.f32 "
        "{%0,%1,%2,%3}, {%4,%5,%6,%7}, {%8,%9}, {%0,%1,%2,%3};"
        : "+f"(d[0]), "+f"(d[1]), "+f"(d[2]), "+f"(d[3])
        : "r"(a[0]), "r"(a[1]), "r"(a[2]), "r"(a[3]), "r"(b0), "r"(b1));
}
// XOR swizzle for 128-row x 32-col fp16 tiles, 16B chunks (4/row), pitch 64B.
// (validated in round 3: conflict-free for this ldmatrix pattern)
__device__ __forceinline__ uint32_t sw32(uint32_t row, uint32_t c) {
    return row * 64u + ((c ^ ((row >> 1) & 3u)) << 4);
}

// ---------------- split fp32 -> (fp16 hi, fp16 lo) ---------------------------
__global__ void __launch_bounds__(256) split_kernel(
    const float4* __restrict__ in, __half2* __restrict__ hi,
    __half2* __restrict__ lo, int n4)
{
    int i = blockIdx.x * 256 + threadIdx.x;
    if (i >= n4) return;
    float4 v = in[i];
    __half hx = __float2half_rn(v.x);
    __half hy = __float2half_rn(v.y);
    __half hz = __float2half_rn(v.z);
    __half hw = __float2half_rn(v.w);
    __half2 h0; h0.x = hx; h0.y = hy;
    __half2 h1; h1.x = hz; h1.y = hw;
    __half2 l0;
    l0.x = __float2half_rn(v.x - __half2float(hx));
    l0.y = __float2half_rn(v.y - __half2float(hy));
    __half2 l1;
    l1.x = __float2half_rn(v.z - __half2float(hz));
    l1.y = __float2half_rn(v.w - __half2float(hw));
    hi[2 * i] = h0; hi[2 * i + 1] = h1;
    lo[2 * i] = l0; lo[2 * i + 1] = l1;
}

// ---------------- pack Wf[:, :1024] -> B rows 0..1023, zero sim bias ----------
__global__ void __launch_bounds__(256) pack_wfx_kernel(
    const float* __restrict__ Wf,          // [1024, 2048]
    __half2* __restrict__ B,               // [1152, 1024] fp16 (rows 0..1023)
    const float* __restrict__ bf,
    float* __restrict__ bias)              // [1152]
{
    int i4 = blockIdx.x * 256 + threadIdx.x;      // float4 idx over 1024x1024
    if (i4 >= DIM * DIM / 4) return;
    int d = i4 >> 8;
    int c = (i4 & 255) * 4;
    float4 v = *reinterpret_cast<const float4*>(&Wf[(size_t)d * (2 * DIM) + c]);
    __half2 a; a.x = __float2half_rn(v.x); a.y = __float2half_rn(v.y);
    __half2 b; b.x = __float2half_rn(v.z); b.y = __float2half_rn(v.w);
    B[2 * i4] = a; B[2 * i4 + 1] = b;
    if (i4 < NW) bias[i4] = (i4 < DIM) ? bf[i4] : 0.f;
}

// ---------------- R = mem @ Wq (exact fp32) -----------------------------------
__global__ void __launch_bounds__(256) rp_r_kernel(
    const float* __restrict__ mem,         // [64, 1024]
    const float* __restrict__ Wq,          // [1024, 1024]
    float* __restrict__ R)                 // [64, 1024]
{
    __shared__ float msf[4 * DIM];
    __shared__ float red[256];
    const int c0 = blockIdx.x * 16;
    const int m0 = blockIdx.y * 4;
    const int tid = threadIdx.x;

    for (int i = tid; i < 4 * DIM; i += 256)
        msf[i] = mem[(size_t)(m0 + (i >> 10)) * DIM + (i & (DIM - 1))];
    __syncthreads();

    const int col = c0 + (tid & 15);
    const int m   = (tid >> 4) & 3;
    const int eg  = tid >> 6;
    const float* mrow = &msf[m * DIM + eg * 256];
    const float* wp = &Wq[(size_t)(eg * 256) * DIM + col];
    float acc = 0.f;
#pragma unroll 8
    for (int i = 0; i < 256; i++)
        acc = fmaf(mrow[i], wp[(size_t)i * DIM], acc);
    red[tid] = acc;
    __syncthreads();
    if (tid < 64) {
        float s = red[tid] + red[tid + 64] + red[tid + 128] + red[tid + 192];
        R[(size_t)(m0 + (tid >> 4)) * DIM + c0 + (tid & 15)] = s;
    }
}

// ---------------- pack R -> B rows 1024..1151 (Rh ; Rl) -----------------------
__global__ void __launch_bounds__(256) pack_r_kernel(
    const float* __restrict__ R,           // [64, 1024]
    __half2* __restrict__ B)               // rows 1024.. (Rh), 1088.. (Rl)
{
    int i4 = blockIdx.x * 256 + threadIdx.x;      // float4 idx over 64x1024
    if (i4 >= MSL * DIM / 4) return;
    int m = i4 >> 8;
    int c = (i4 & 255) * 4;
    float4 v = *reinterpret_cast<const float4*>(&R[(size_t)m * DIM + c]);
    __half hx = __float2half_rn(v.x);
    __half hy = __float2half_rn(v.y);
    __half hz = __float2half_rn(v.z);
    __half hw = __float2half_rn(v.w);
    __half2 h0; h0.x = hx; h0.y = hy;
    __half2 h1; h1.x = hz; h1.y = hw;
    __half2 l0;
    l0.x = __float2half_rn(v.x - __half2float(hx));
    l0.y = __float2half_rn(v.y - __half2float(hy));
    __half2 l1;
    l1.x = __float2half_rn(v.z - __half2float(hz));
    l1.y = __float2half_rn(v.w - __half2float(hw));
    size_t hb = ((size_t)(DIM + m) * DIM + c) >> 1;        // Rh row
    size_t lb = ((size_t)(DIM + MSL + m) * DIM + c) >> 1;  // Rl row
    B[hb] = h0; B[hb + 1] = h1;
    B[lb] = l0; B[lb + 1] = l1;
}

// ---------------- P = mem @ Wf[:,1024:]^T (exact fp32) ------------------------
__global__ void __launch_bounds__(256) rp_p_kernel(
    const float* __restrict__ mem,
    const float* __restrict__ Wf,
    float* __restrict__ P)
{
    __shared__ float msf[4 * DIM];
    const int d0 = blockIdx.x * 16;
    const int m0 = blockIdx.y * 4;
    const int tid = threadIdx.x;

    for (int i = tid; i < 4 * DIM; i += 256)
        msf[i] = mem[(size_t)(m0 + (i >> 10)) * DIM + (i & (DIM - 1))];
    __syncthreads();

    const int d  = d0 + (tid >> 4);
    const int el = tid & 15;
    const float* wrow = &Wf[(size_t)d * (2 * DIM) + DIM];
    float acc0 = 0.f, acc1 = 0.f, acc2 = 0.f, acc3 = 0.f;
#pragma unroll 8
    for (int i = 0; i < 64; i++) {
        int e = el + i * 16;
        float w = wrow[e];
        acc0 = fmaf(msf[e],           w, acc0);
        acc1 = fmaf(msf[DIM + e],     w, acc1);
        acc2 = fmaf(msf[2 * DIM + e], w, acc2);
        acc3 = fmaf(msf[3 * DIM + e], w, acc3);
    }
#pragma unroll
    for (int o = 8; o; o >>= 1) {
        acc0 += __shfl_down_sync(0xffffffffu, acc0, o, 16);
        acc1 += __shfl_down_sync(0xffffffffu, acc1, o, 16);
        acc2 += __shfl_down_sync(0xffffffffu, acc2, o, 16);
        acc3 += __shfl_down_sync(0xffffffffu, acc3, o, 16);
    }
    if (el == 0) {
        P[(size_t)m0 * DIM + d] = acc0;
        P[(size_t)(m0 + 1) * DIM + d] = acc1;
        P[(size_t)(m0 + 2) * DIM + d] = acc2;
        P[(size_t)(m0 + 3) * DIM + d] = acc3;
    }
}

// ---------------- c = mem @ bq ------------------------------------------------
__global__ void __launch_bounds__(256) cvec_kernel(
    const float* __restrict__ mem, const float* __restrict__ bq,
    float* __restrict__ c)
{
    const int warp = threadIdx.x >> 5, lane = threadIdx.x & 31;
    const int m = blockIdx.x * 8 + warp;
    const float4* mr = reinterpret_cast<const float4*>(mem + (size_t)m * DIM);
    const float4* bv = reinterpret_cast<const float4*>(bq);
    float s = 0.f;
#pragma unroll
    for (int i = 0; i < 8; i++) {
        float4 a = mr[lane + i * 32];
        float4 b = bv[lane + i * 32];
        s = fmaf(a.x, b.x, s); s = fmaf(a.y, b.y, s);
        s = fmaf(a.z, b.z, s); s = fmaf(a.w, b.w, s);
    }
#pragma unroll
    for (int o = 16; o; o >>= 1) s += __shfl_xor_sync(0xffffffffu, s, o);
    if (lane == 0) c[m] = s;
}

// ---------------- fp16x2 HMMA GEMM: C = x @ B^T + bias ------------------------
// CTA 128(M) x 128(N), BK=32, 4-stage ring (96 KB), 2 CTAs/SM.
#define GBM 128
#define GBN 128
#define GBK 32
#define TILE_B 8192u                      // 128x32 fp16 tile
#define OFF_AH 0u
#define OFF_AL (TILE_B)
#define OFF_B  (2u * TILE_B)
#define STAGE_B (3u * TILE_B)             // 24 KB
#define NSTAGE 4
#define GEMM_SMEM (NSTAGE * STAGE_B)      // 96 KB

__global__ void __launch_bounds__(256, 2) gemm_fp16x2_kernel(
    const __half* __restrict__ Ah, const __half* __restrict__ Al,
    const __half* __restrict__ B,          // [1152, 1024] fp16
    const float* __restrict__ bias,        // [1152]
    float* __restrict__ C)                 // [16384, 1152]
{
    extern __shared__ char smem[];
    const uint32_t sb = smem_u32(smem);
    const int tid = threadIdx.x;
    const int wid = tid >> 5;
    const int lane = tid & 31;
    const int n0 = blockIdx.y * GBM;
    const int e0 = blockIdx.x * GBN;
    const int nchunk = DIM / GBK;          // 32

    const uint32_t warp_m = (uint32_t)(wid >> 2) * 64u;
    const uint32_t warp_n = (uint32_t)(wid & 3) * 32u;

    float acc[4][4][4];
#pragma unroll
    for (int mt = 0; mt < 4; mt++)
#pragma unroll
        for (int nt = 0; nt < 4; nt++)
#pragma unroll
            for (int j = 0; j < 4; j++) acc[mt][nt][j] = 0.f;

    auto load_stage = [&](int i, int s) {
        const int kt = i * GBK;
        const uint32_t sbase = sb + (uint32_t)s * STAGE_B;
#pragma unroll
        for (int j = 0; j < 2; j++) {
            int g = tid + j * 256;                 // 0..511
            uint32_t r = (uint32_t)(g >> 2);
            uint32_t cc = (uint32_t)(g & 3);
            uint32_t so = sw32(r, cc);
            cpasync16(sbase + OFF_AH + so, Ah + (size_t)(n0 + r) * DIM + kt + cc * 8);
            cpasync16(sbase + OFF_AL + so, Al + (size_t)(n0 + r) * DIM + kt + cc * 8);
            cpasync16(sbase + OFF_B  + so, B  + (size_t)(e0 + r) * DIM + kt + cc * 8);
        }
    };

    load_stage(0, 0); cp_commit();
    load_stage(1, 1); cp_commit();
    load_stage(2, 2); cp_commit();

    for (int i = 0; i < nchunk; i++) {
        cp_wait2();                 // stage i landed
        __syncthreads();            // all warps done with stage (i+3)&3
        if (i + 3 < nchunk) load_stage(i + 3, (i + 3) & 3);
        cp_commit();

        const uint32_t base = sb + (uint32_t)(i & 3) * STAGE_B;
#pragma unroll
        for (int k16 = 0; k16 < 2; k16++) {
            uint32_t ah[4][4], al[4][4];
            const uint32_t arow = (uint32_t)(lane & 15);
            const uint32_t acnk = (uint32_t)(2 * k16 + (lane >> 4));
#pragma unroll
            for (int mt = 0; mt < 4; mt++) {
                uint32_t so = sw32(warp_m + (uint32_t)mt * 16u + arow, acnk);
                ldsm4(ah[mt], base + OFF_AH + so);
                ldsm4(al[mt], base + OFF_AL + so);
            }
            uint32_t bf[4][2];
            const uint32_t brow0 = (uint32_t)((lane & 7) + ((lane >> 4) & 1) * 8);
            const uint32_t bcnk  = (uint32_t)(2 * k16 + ((lane >> 3) & 1));
#pragma unroll
            for (int half = 0; half < 2; half++) {
                uint32_t so = sw32(warp_n + (uint32_t)half * 16u + brow0, bcnk);
                uint32_t t[4];
                ldsm4(t, base + OFF_B + so);
                bf[2 * half][0] = t[0];     bf[2 * half][1] = t[1];
                bf[2 * half + 1][0] = t[2]; bf[2 * half + 1][1] = t[3];
            }
#pragma unroll
            for (int mt = 0; mt < 4; mt++) {
#pragma unroll
                for (int nt = 0; nt < 4; nt++) {
                    mma16816(acc[mt][nt], ah[mt], bf[nt][0], bf[nt][1]);
                    mma16816(acc[mt][nt], al[mt], bf[nt][0], bf[nt][1]);
                }
            }
        }
    }

#pragma unroll
    for (int mt = 0; mt < 4; mt++) {
#pragma unroll
        for (int nt = 0; nt < 4; nt++) {
            int row = n0 + (int)warp_m + mt * 16 + (lane >> 2);
            int col = e0 + (int)warp_n + nt * 8 + (lane & 3) * 2;
            float b0 = bias[col], b1 = bias[col + 1];
            float2 v0; v0.x = acc[mt][nt][0] + b0; v0.y = acc[mt][nt][1] + b1;
            float2 v1; v1.x = acc[mt][nt][2] + b0; v1.y = acc[mt][nt][3] + b1;
            *reinterpret_cast<float2*>(&C[(size_t)row * NW + col]) = v0;
            *reinterpret_cast<float2*>(&C[(size_t)(row + 8) * NW + col]) = v1;
        }
    }
}

// ---------------- tail: sim strips -> top3 -> H = Hx + sum w P -> LN+ReLU -----
__global__ void __launch_bounds__(256) tail_kernel(
    const float* __restrict__ C,           // [16384, 1152]
    const float* __restrict__ c,           // [64]
    const float* __restrict__ P,           // [64, 1024]
    const float* __restrict__ gamma,
    const float* __restrict__ beta,
    float* __restrict__ out)
{
    const int n = blockIdx.x;
    const int tid = threadIdx.x;
    const int lane = tid & 31;
    const int warp = tid >> 5;

    __shared__ float sim_s[MSL];
    __shared__ float wgt[KTOP];
    __shared__ int   sidx[KTOP];
    __shared__ float sh_s[8], sh_ss[8];

    const float* crow = C + (size_t)n * NW;
    if (tid < MSL)
        sim_s[tid] = crow[DIM + tid] + crow[DIM + MSL + tid] + c[tid];
    __syncthreads();

    if (tid == 0) {
        float v0 = -3.4e38f, v1 = -3.4e38f, v2 = -3.4e38f;
        int i0 = 0, i1 = 0, i2 = 0;
        for (int m = 0; m < MSL; m++) {
            float v = sim_s[m];
            if (v > v0)      { v2 = v1; i2 = i1; v1 = v0; i1 = i0; v0 = v; i0 = m; }
            else if (v > v1) { v2 = v1; i2 = i1; v1 = v;  i1 = m; }
            else if (v > v2) { v2 = v;  i2 = m; }
        }
        float e1 = __expf(v1 - v0);
        float e2 = __expf(v2 - v0);
        float inv = 1.f / (1.f + e1 + e2);
        wgt[0] = inv; wgt[1] = e1 * inv; wgt[2] = e2 * inv;
        sidx[0] = i0; sidx[1] = i1; sidx[2] = i2;
    }
    __syncthreads();

    const float w0 = wgt[0], w1 = wgt[1], w2 = wgt[2];
    float4 v  = reinterpret_cast<const float4*>(crow)[tid];
    float4 p0 = reinterpret_cast<const float4*>(P + (size_t)sidx[0] * DIM)[tid];
    float4 p1 = reinterpret_cast<const float4*>(P + (size_t)sidx[1] * DIM)[tid];
    float4 p2 = reinterpret_cast<const float4*>(P + (size_t)sidx[2] * DIM)[tid];
    v.x += w0 * p0.x + w1 * p1.x + w2 * p2.x;
    v.y += w0 * p0.y + w1 * p1.y + w2 * p2.y;
    v.z += w0 * p0.z + w1 * p1.z + w2 * p2.z;
    v.w += w0 * p0.w + w1 * p1.w + w2 * p2.w;

    float s  = v.x + v.y + v.z + v.w;
    float ss = v.x * v.x + v.y * v.y + v.z * v.z + v.w * v.w;
#pragma unroll
    for (int o = 16; o; o >>= 1) {
        s  += __shfl_xor_sync(0xffffffffu, s, o);
        ss += __shfl_xor_sync(0xffffffffu, ss, o);
    }
    if (lane == 0) { sh_s[warp] = s; sh_ss[warp] = ss; }
    __syncthreads();
    if (warp == 0) {
        s  = (lane < 8) ? sh_s[lane]  : 0.f;
        ss = (lane < 8) ? sh_ss[lane] : 0.f;
#pragma unroll
        for (int o = 4; o; o >>= 1) {
            s  += __shfl_xor_sync(0xffffffffu, s, o);
            ss += __shfl_xor_sync(0xffffffffu, ss, o);
        }
        if (lane == 0) { sh_s[0] = s; sh_ss[0] = ss; }
    }
    __syncthreads();

    const float mean = sh_s[0] * (1.f / DIM);
    const float var  = sh_ss[0] * (1.f / DIM) - mean * mean;
    const float rstd = rsqrtf(var + LN_EPS);
    float4 g = reinterpret_cast<const float4*>(gamma)[tid];
    float4 bb = reinterpret_cast<const float4*>(beta)[tid];
    float4 o;
    o.x = fmaxf((v.x - mean) * rstd * g.x + bb.x, 0.f);
    o.y = fmaxf((v.y - mean) * rstd * g.y + bb.y, 0.f);
    o.z = fmaxf((v.z - mean) * rstd * g.z + bb.z, 0.f);
    o.w = fmaxf((v.w - mean) * rstd * g.w + bb.w, 0.f);
    reinterpret_cast<float4*>(out + (size_t)n * DIM)[tid] = o;
}

// ---------------- host --------------------------------------------------------
extern "C" void kernel_launch(void* const* d_in, const int* in_sizes, int n_in,
                              void* d_out, int out_size)
{
    const float* x      = (const float*)d_in[0];
    const float* memory = (const float*)d_in[1];
    const float* Wq     = (const float*)d_in[2];
    const float* bq     = (const float*)d_in[3];
    const float* Wf     = (const float*)d_in[4];
    const float* bf     = (const float*)d_in[5];
    const float* gamma  = (const float*)d_in[6];
    const float* beta   = (const float*)d_in[7];
    float* out = (float*)d_out;

    void *xh, *xl, *B, *bias, *R, *c, *P, *C;
    cudaGetSymbolAddress(&xh, g_xh);   cudaGetSymbolAddress(&xl, g_xl);
    cudaGetSymbolAddress(&B,  g_B);    cudaGetSymbolAddress(&bias, g_bias);
    cudaGetSymbolAddress(&R,  g_R);    cudaGetSymbolAddress(&c,  g_c);
    cudaGetSymbolAddress(&P,  g_P);    cudaGetSymbolAddress(&C,  g_C);

    static cudaStream_t s1 = nullptr, s2 = nullptr;
    static cudaEvent_t evRoot = nullptr, evWB = nullptr, evRB = nullptr, evAux = nullptr;
    static bool init_done = false;
    if (!init_done) {
        cudaFuncSetAttribute(gemm_fp16x2_kernel,
                             cudaFuncAttributeMaxDynamicSharedMemorySize, GEMM_SMEM);
        cudaStreamCreateWithFlags(&s1, cudaStreamNonBlocking);
        cudaStreamCreateWithFlags(&s2, cudaStreamNonBlocking);
        cudaEventCreateWithFlags(&evRoot, cudaEventDisableTiming);
        cudaEventCreateWithFlags(&evWB,   cudaEventDisableTiming);
        cudaEventCreateWithFlags(&evRB,   cudaEventDisableTiming);
        cudaEventCreateWithFlags(&evAux,  cudaEventDisableTiming);
        init_done = true;
    }

    // fork side branches off the captured legacy stream
    cudaEventRecord(evRoot, 0);
    cudaStreamWaitEvent(s1, evRoot, 0);
    cudaStreamWaitEvent(s2, evRoot, 0);

    // branch s1: R -> pack into B rows 1024..1151
    rp_r_kernel<<<dim3(64, 16), 256, 0, s1>>>(memory, Wq, (float*)R);
    pack_r_kernel<<<MSL * DIM / 4 / 256, 256, 0, s1>>>((const float*)R, (__half2*)B);
    cudaEventRecord(evRB, s1);

    // branch s2: Wf_x pack -> B rows 0..1023 (+bias); then P and c (tail deps)
    pack_wfx_kernel<<<DIM * DIM / 4 / 256, 256, 0, s2>>>(Wf, (__half2*)B, bf,
                                                         (float*)bias);
    cudaEventRecord(evWB, s2);
    rp_p_kernel<<<dim3(64, 16), 256, 0, s2>>>(memory, Wf, (float*)P);
    cvec_kernel<<<8, 256, 0, s2>>>(memory, bq, (float*)c);
    cudaEventRecord(evAux, s2);

    // main: x split -> GEMM (needs both B halves)
    split_kernel<<<NTOK * DIM / 4 / 256, 256>>>(
        (const float4*)x, (__half2*)xh, (__half2*)xl, NTOK * DIM / 4);
    cudaStreamWaitEvent(0, evWB, 0);
    cudaStreamWaitEvent(0, evRB, 0);
    dim3 gg(NW / GBN, NTOK / GBM);   // (9, 128)
    gemm_fp16x2_kernel<<<gg, 256, GEMM_SMEM>>>(
        (const __half*)xh, (const __half*)xl,
        (const __half*)B, (const float*)bias, (float*)C);

    // join: tail needs C, c, P
    cudaStreamWaitEvent(0, evAux, 0);
    tail_kernel<<<NTOK, 256>>>((const float*)C, (const float*)c,
                               (const float*)P, gamma, beta, out);
}

// round 10
// speedup vs baseline: 11.0332x; 1.4057x over previous
#include <cuda_runtime.h>
#include <cuda_fp16.h>
#include <math.h>
#include <stdint.h>

#define NTOK (8 * 2048)      // 16384 rows
#define DIM  1024
#define NW   1152            // GEMM output width: 1024 Hx | 64 simH | 64 simL
#define MSL  64
#define KTOP 3
#define LN_EPS 1e-5f

// ---------------- scratch (allocation-free rule: __device__ globals) -------
__device__ __half g_xh[(size_t)NTOK * DIM];       // x rounded to fp16
__device__ __half g_B[(size_t)NW * DIM];          // [Wf_x ; Rh ; Rl] fp16
__device__ float g_bias[NW];                      // [bf | 0...]
__device__ float g_R[(size_t)MSL * DIM];          // mem @ Wq     (exact fp32)
__device__ float g_c[MSL];                        // mem @ bq
__device__ float g_P[(size_t)MSL * DIM];          // mem @ Wf_m^T (exact fp32)
__device__ float g_C[(size_t)NTOK * NW];          // GEMM out

// ---------------- helpers ----------------------------------------------------
__device__ __forceinline__ uint32_t smem_u32(const void* p) {
    uint32_t a;
    asm("{ .reg .u64 t; cvta.to.shared.u64 t, %1; cvt.u32.u64 %0, t; }" : "=r"(a) : "l"(p));
    return a;
}
__device__ __forceinline__ void cpasync16(uint32_t s, const void* g) {
    asm volatile("cp.async.cg.shared.global [%0], [%1], 16;" :: "r"(s), "l"(g));
}
__device__ __forceinline__ void cp_commit() {
    asm volatile("cp.async.commit_group;");
}
__device__ __forceinline__ void cp_wait4() {
    asm volatile("cp.async.wait_group 4;");
}
__device__ __forceinline__ void ldsm4(uint32_t* t, uint32_t addr) {
    asm volatile("ldmatrix.sync.aligned.m8n8.x4.shared.b16 {%0,%1,%2,%3}, [%4];"
        : "=r"(t[0]), "=r"(t[1]), "=r"(t[2]), "=r"(t[3]) : "r"(addr));
}
__device__ __forceinline__ void mma16816(float* d, const uint32_t* a,
                                         uint32_t b0, uint32_t b1) {
    asm volatile(
        "mma.sync.aligned.m16n8k16.row.col.f32.f16.f16.f32 "
        "{%0,%1,%2,%3}, {%4,%5,%6,%7}, {%8,%9}, {%0,%1,%2,%3};"
        : "+f"(d[0]), "+f"(d[1]), "+f"(d[2]), "+f"(d[3])
        : "r"(a[0]), "r"(a[1]), "r"(a[2]), "r"(a[3]), "r"(b0), "r"(b1));
}
// XOR swizzle for 128-row x 32-col fp16 tiles, 16B chunks (4/row), pitch 64B.
__device__ __forceinline__ uint32_t sw32(uint32_t row, uint32_t c) {
    return row * 64u + ((c ^ ((row >> 1) & 3u)) << 4);
}

// ---------------- round x -> fp16 ---------------------------------------------
__global__ void __launch_bounds__(256) round_x_kernel(
    const float4* __restrict__ in, __half2* __restrict__ o, int n4)
{
    int i = blockIdx.x * 256 + threadIdx.x;
    if (i >= n4) return;
    float4 v = in[i];
    __half2 a; a.x = __float2half_rn(v.x); a.y = __float2half_rn(v.y);
    __half2 b; b.x = __float2half_rn(v.z); b.y = __float2half_rn(v.w);
    o[2 * i] = a; o[2 * i + 1] = b;
}

// ---------------- pack Wf[:, :1024] -> B rows 0..1023, bias -------------------
__global__ void __launch_bounds__(256) pack_wfx_kernel(
    const float* __restrict__ Wf,          // [1024, 2048]
    __half2* __restrict__ B,
    const float* __restrict__ bf,
    float* __restrict__ bias)              // [1152]
{
    int i4 = blockIdx.x * 256 + threadIdx.x;
    if (i4 >= DIM * DIM / 4) return;
    int d = i4 >> 8;
    int c = (i4 & 255) * 4;
    float4 v = *reinterpret_cast<const float4*>(&Wf[(size_t)d * (2 * DIM) + c]);
    __half2 a; a.x = __float2half_rn(v.x); a.y = __float2half_rn(v.y);
    __half2 b; b.x = __float2half_rn(v.z); b.y = __float2half_rn(v.w);
    B[2 * i4] = a; B[2 * i4 + 1] = b;
    if (i4 < NW) bias[i4] = (i4 < DIM) ? bf[i4] : 0.f;
}

// ---------------- R = mem @ Wq (exact fp32) -----------------------------------
__global__ void __launch_bounds__(256) rp_r_kernel(
    const float* __restrict__ mem,
    const float* __restrict__ Wq,
    float* __restrict__ R)
{
    __shared__ float msf[4 * DIM];
    __shared__ float red[256];
    const int c0 = blockIdx.x * 16;
    const int m0 = blockIdx.y * 4;
    const int tid = threadIdx.x;

    for (int i = tid; i < 4 * DIM; i += 256)
        msf[i] = mem[(size_t)(m0 + (i >> 10)) * DIM + (i & (DIM - 1))];
    __syncthreads();

    const int col = c0 + (tid & 15);
    const int m   = (tid >> 4) & 3;
    const int eg  = tid >> 6;
    const float* mrow = &msf[m * DIM + eg * 256];
    const float* wp = &Wq[(size_t)(eg * 256) * DIM + col];
    float acc = 0.f;
#pragma unroll 8
    for (int i = 0; i < 256; i++)
        acc = fmaf(mrow[i], wp[(size_t)i * DIM], acc);
    red[tid] = acc;
    __syncthreads();
    if (tid < 64) {
        float s = red[tid] + red[tid + 64] + red[tid + 128] + red[tid + 192];
        R[(size_t)(m0 + (tid >> 4)) * DIM + c0 + (tid & 15)] = s;
    }
}

// ---------------- pack R -> B rows 1024..1151 (Rh ; Rl) -----------------------
__global__ void __launch_bounds__(256) pack_r_kernel(
    const float* __restrict__ R,
    __half2* __restrict__ B)
{
    int i4 = blockIdx.x * 256 + threadIdx.x;
    if (i4 >= MSL * DIM / 4) return;
    int m = i4 >> 8;
    int c = (i4 & 255) * 4;
    float4 v = *reinterpret_cast<const float4*>(&R[(size_t)m * DIM + c]);
    __half hx = __float2half_rn(v.x);
    __half hy = __float2half_rn(v.y);
    __half hz = __float2half_rn(v.z);
    __half hw = __float2half_rn(v.w);
    __half2 h0; h0.x = hx; h0.y = hy;
    __half2 h1; h1.x = hz; h1.y = hw;
    __half2 l0;
    l0.x = __float2half_rn(v.x - __half2float(hx));
    l0.y = __float2half_rn(v.y - __half2float(hy));
    __half2 l1;
    l1.x = __float2half_rn(v.z - __half2float(hz));
    l1.y = __float2half_rn(v.w - __half2float(hw));
    size_t hb = ((size_t)(DIM + m) * DIM + c) >> 1;
    size_t lb = ((size_t)(DIM + MSL + m) * DIM + c) >> 1;
    B[hb] = h0; B[hb + 1] = h1;
    B[lb] = l0; B[lb + 1] = l1;
}

// ---------------- P = mem @ Wf[:,1024:]^T (exact fp32) ------------------------
__global__ void __launch_bounds__(256) rp_p_kernel(
    const float* __restrict__ mem,
    const float* __restrict__ Wf,
    float* __restrict__ P)
{
    __shared__ float msf[4 * DIM];
    const int d0 = blockIdx.x * 16;
    const int m0 = blockIdx.y * 4;
    const int tid = threadIdx.x;

    for (int i = tid; i < 4 * DIM; i += 256)
        msf[i] = mem[(size_t)(m0 + (i >> 10)) * DIM + (i & (DIM - 1))];
    __syncthreads();

    const int d  = d0 + (tid >> 4);
    const int el = tid & 15;
    const float* wrow = &Wf[(size_t)d * (2 * DIM) + DIM];
    float acc0 = 0.f, acc1 = 0.f, acc2 = 0.f, acc3 = 0.f;
#pragma unroll 8
    for (int i = 0; i < 64; i++) {
        int e = el + i * 16;
        float w = wrow[e];
        acc0 = fmaf(msf[e],           w, acc0);
        acc1 = fmaf(msf[DIM + e],     w, acc1);
        acc2 = fmaf(msf[2 * DIM + e], w, acc2);
        acc3 = fmaf(msf[3 * DIM + e], w, acc3);
    }
#pragma unroll
    for (int o = 8; o; o >>= 1) {
        acc0 += __shfl_down_sync(0xffffffffu, acc0, o, 16);
        acc1 += __shfl_down_sync(0xffffffffu, acc1, o, 16);
        acc2 += __shfl_down_sync(0xffffffffu, acc2, o, 16);
        acc3 += __shfl_down_sync(0xffffffffu, acc3, o, 16);
    }
    if (el == 0) {
        P[(size_t)m0 * DIM + d] = acc0;
        P[(size_t)(m0 + 1) * DIM + d] = acc1;
        P[(size_t)(m0 + 2) * DIM + d] = acc2;
        P[(size_t)(m0 + 3) * DIM + d] = acc3;
    }
}

// ---------------- c = mem @ bq ------------------------------------------------
__global__ void __launch_bounds__(256) cvec_kernel(
    const float* __restrict__ mem, const float* __restrict__ bq,
    float* __restrict__ c)
{
    const int warp = threadIdx.x >> 5, lane = threadIdx.x & 31;
    const int m = blockIdx.x * 8 + warp;
    const float4* mr = reinterpret_cast<const float4*>(mem + (size_t)m * DIM);
    const float4* bv = reinterpret_cast<const float4*>(bq);
    float s = 0.f;
#pragma unroll
    for (int i = 0; i < 8; i++) {
        float4 a = mr[lane + i * 32];
        float4 b = bv[lane + i * 32];
        s = fmaf(a.x, b.x, s); s = fmaf(a.y, b.y, s);
        s = fmaf(a.z, b.z, s); s = fmaf(a.w, b.w, s);
    }
#pragma unroll
    for (int o = 16; o; o >>= 1) s += __shfl_xor_sync(0xffffffffu, s, o);
    if (lane == 0) c[m] = s;
}

// ---------------- fp16 HMMA GEMM: C = x16 @ B^T + bias (single pass) ----------
// CTA 128(M) x 128(N), BK=32, 6-stage ring (96 KB), 2 CTAs/SM.
#define GBM 128
#define GBN 128
#define GBK 32
#define TILE_B 8192u                      // 128x32 fp16 tile
#define OFF_A  0u
#define OFF_B  (TILE_B)
#define STAGE_B (2u * TILE_B)             // 16 KB
#define NSTAGE 6
#define GEMM_SMEM (NSTAGE * STAGE_B)      // 96 KB

__global__ void __launch_bounds__(256, 2) gemm_fp16_kernel(
    const __half* __restrict__ A,          // [16384, 1024] fp16
    const __half* __restrict__ B,          // [1152, 1024] fp16
    const float* __restrict__ bias,        // [1152]
    float* __restrict__ C)                 // [16384, 1152]
{
    extern __shared__ char smem[];
    const uint32_t sb = smem_u32(smem);
    const int tid = threadIdx.x;
    const int wid = tid >> 5;
    const int lane = tid & 31;
    const int n0 = blockIdx.y * GBM;
    const int e0 = blockIdx.x * GBN;
    const int nchunk = DIM / GBK;          // 32

    const uint32_t warp_m = (uint32_t)(wid >> 2) * 64u;
    const uint32_t warp_n = (uint32_t)(wid & 3) * 32u;

    float acc[4][4][4];
#pragma unroll
    for (int mt = 0; mt < 4; mt++)
#pragma unroll
        for (int nt = 0; nt < 4; nt++)
#pragma unroll
            for (int j = 0; j < 4; j++) acc[mt][nt][j] = 0.f;

    auto load_stage = [&](int i, int s) {
        const int kt = i * GBK;
        const uint32_t sbase = sb + (uint32_t)s * STAGE_B;
#pragma unroll
        for (int j = 0; j < 2; j++) {
            int g = tid + j * 256;                 // 0..511
            uint32_t r = (uint32_t)(g >> 2);
            uint32_t cc = (uint32_t)(g & 3);
            uint32_t so = sw32(r, cc);
            cpasync16(sbase + OFF_A + so, A + (size_t)(n0 + r) * DIM + kt + cc * 8);
            cpasync16(sbase + OFF_B + so, B + (size_t)(e0 + r) * DIM + kt + cc * 8);
        }
    };

    load_stage(0, 0); cp_commit();
    load_stage(1, 1); cp_commit();
    load_stage(2, 2); cp_commit();
    load_stage(3, 3); cp_commit();
    load_stage(4, 4); cp_commit();

    int cs = 0;                           // compute stage
    int ls = 5;                           // next load stage
    for (int i = 0; i < nchunk; i++) {
        cp_wait4();                 // stage i landed (5 in flight -> oldest done)
        __syncthreads();
        if (i + 5 < nchunk) load_stage(i + 5, ls);
        cp_commit();

        const uint32_t base = sb + (uint32_t)cs * STAGE_B;
#pragma unroll
        for (int k16 = 0; k16 < 2; k16++) {
            uint32_t af[4][4];
            const uint32_t arow = (uint32_t)(lane & 15);
            const uint32_t acnk = (uint32_t)(2 * k16 + (lane >> 4));
#pragma unroll
            for (int mt = 0; mt < 4; mt++) {
                uint32_t so = sw32(warp_m + (uint32_t)mt * 16u + arow, acnk);
                ldsm4(af[mt], base + OFF_A + so);
            }
            uint32_t bf[4][2];
            const uint32_t brow0 = (uint32_t)((lane & 7) + ((lane >> 4) & 1) * 8);
            const uint32_t bcnk  = (uint32_t)(2 * k16 + ((lane >> 3) & 1));
#pragma unroll
            for (int half = 0; half < 2; half++) {
                uint32_t so = sw32(warp_n + (uint32_t)half * 16u + brow0, bcnk);
                uint32_t t[4];
                ldsm4(t, base + OFF_B + so);
                bf[2 * half][0] = t[0];     bf[2 * half][1] = t[1];
                bf[2 * half + 1][0] = t[2]; bf[2 * half + 1][1] = t[3];
            }
#pragma unroll
            for (int mt = 0; mt < 4; mt++) {
#pragma unroll
                for (int nt = 0; nt < 4; nt++)
                    mma16816(acc[mt][nt], af[mt], bf[nt][0], bf[nt][1]);
            }
        }
        cs = (cs + 1 == NSTAGE) ? 0 : cs + 1;
        ls = (ls + 1 == NSTAGE) ? 0 : ls + 1;
    }

#pragma unroll
    for (int mt = 0; mt < 4; mt++) {
#pragma unroll
        for (int nt = 0; nt < 4; nt++) {
            int row = n0 + (int)warp_m + mt * 16 + (lane >> 2);
            int col = e0 + (int)warp_n + nt * 8 + (lane & 3) * 2;
            float b0 = bias[col], b1 = bias[col + 1];
            float2 v0; v0.x = acc[mt][nt][0] + b0; v0.y = acc[mt][nt][1] + b1;
            float2 v1; v1.x = acc[mt][nt][2] + b0; v1.y = acc[mt][nt][3] + b1;
            *reinterpret_cast<float2*>(&C[(size_t)row * NW + col]) = v0;
            *reinterpret_cast<float2*>(&C[(size_t)(row + 8) * NW + col]) = v1;
        }
    }
}

// ---------------- tail: sim strips -> top3 -> H = Hx + sum w P -> LN+ReLU -----
__global__ void __launch_bounds__(256) tail_kernel(
    const float* __restrict__ C,           // [16384, 1152]
    const float* __restrict__ c,           // [64]
    const float* __restrict__ P,           // [64, 1024]
    const float* __restrict__ gamma,
    const float* __restrict__ beta,
    float* __restrict__ out)
{
    const int n = blockIdx.x;
    const int tid = threadIdx.x;
    const int lane = tid & 31;
    const int warp = tid >> 5;

    __shared__ float sim_s[MSL];
    __shared__ float wgt[KTOP];
    __shared__ int   sidx[KTOP];
    __shared__ float sh_s[8], sh_ss[8];

    const float* crow = C + (size_t)n * NW;
    if (tid < MSL)
        sim_s[tid] = crow[DIM + tid] + crow[DIM + MSL + tid] + c[tid];
    __syncthreads();

    if (tid == 0) {
        float v0 = -3.4e38f, v1 = -3.4e38f, v2 = -3.4e38f;
        int i0 = 0, i1 = 0, i2 = 0;
        for (int m = 0; m < MSL; m++) {
            float v = sim_s[m];
            if (v > v0)      { v2 = v1; i2 = i1; v1 = v0; i1 = i0; v0 = v; i0 = m; }
            else if (v > v1) { v2 = v1; i2 = i1; v1 = v;  i1 = m; }
            else if (v > v2) { v2 = v;  i2 = m; }
        }
        float e1 = __expf(v1 - v0);
        float e2 = __expf(v2 - v0);
        float inv = 1.f / (1.f + e1 + e2);
        wgt[0] = inv; wgt[1] = e1 * inv; wgt[2] = e2 * inv;
        sidx[0] = i0; sidx[1] = i1; sidx[2] = i2;
    }
    __syncthreads();

    const float w0 = wgt[0], w1 = wgt[1], w2 = wgt[2];
    float4 v  = reinterpret_cast<const float4*>(crow)[tid];
    float4 p0 = reinterpret_cast<const float4*>(P + (size_t)sidx[0] * DIM)[tid];
    float4 p1 = reinterpret_cast<const float4*>(P + (size_t)sidx[1] * DIM)[tid];
    float4 p2 = reinterpret_cast<const float4*>(P + (size_t)sidx[2] * DIM)[tid];
    v.x += w0 * p0.x + w1 * p1.x + w2 * p2.x;
    v.y += w0 * p0.y + w1 * p1.y + w2 * p2.y;
    v.z += w0 * p0.z + w1 * p1.z + w2 * p2.z;
    v.w += w0 * p0.w + w1 * p1.w + w2 * p2.w;

    float s  = v.x + v.y + v.z + v.w;
    float ss = v.x * v.x + v.y * v.y + v.z * v.z + v.w * v.w;
#pragma unroll
    for (int o = 16; o; o >>= 1) {
        s  += __shfl_xor_sync(0xffffffffu, s, o);
        ss += __shfl_xor_sync(0xffffffffu, ss, o);
    }
    if (lane == 0) { sh_s[warp] = s; sh_ss[warp] = ss; }
    __syncthreads();
    if (warp == 0) {
        s  = (lane < 8) ? sh_s[lane]  : 0.f;
        ss = (lane < 8) ? sh_ss[lane] : 0.f;
#pragma unroll
        for (int o = 4; o; o >>= 1) {
            s  += __shfl_xor_sync(0xffffffffu, s, o);
            ss += __shfl_xor_sync(0xffffffffu, ss, o);
        }
        if (lane == 0) { sh_s[0] = s; sh_ss[0] = ss; }
    }
    __syncthreads();

    const float mean = sh_s[0] * (1.f / DIM);
    const float var  = sh_ss[0] * (1.f / DIM) - mean * mean;
    const float rstd = rsqrtf(var + LN_EPS);
    float4 g = reinterpret_cast<const float4*>(gamma)[tid];
    float4 bb = reinterpret_cast<const float4*>(beta)[tid];
    float4 o;
    o.x = fmaxf((v.x - mean) * rstd * g.x + bb.x, 0.f);
    o.y = fmaxf((v.y - mean) * rstd * g.y + bb.y, 0.f);
    o.z = fmaxf((v.z - mean) * rstd * g.z + bb.z, 0.f);
    o.w = fmaxf((v.w - mean) * rstd * g.w + bb.w, 0.f);
    reinterpret_cast<float4*>(out + (size_t)n * DIM)[tid] = o;
}

// ---------------- host --------------------------------------------------------
extern "C" void kernel_launch(void* const* d_in, const int* in_sizes, int n_in,
                              void* d_out, int out_size)
{
    const float* x      = (const float*)d_in[0];
    const float* memory = (const float*)d_in[1];
    const float* Wq     = (const float*)d_in[2];
    const float* bq     = (const float*)d_in[3];
    const float* Wf     = (const float*)d_in[4];
    const float* bf     = (const float*)d_in[5];
    const float* gamma  = (const float*)d_in[6];
    const float* beta   = (const float*)d_in[7];
    float* out = (float*)d_out;

    void *xh, *B, *bias, *R, *c, *P, *C;
    cudaGetSymbolAddress(&xh, g_xh);
    cudaGetSymbolAddress(&B,  g_B);    cudaGetSymbolAddress(&bias, g_bias);
    cudaGetSymbolAddress(&R,  g_R);    cudaGetSymbolAddress(&c,  g_c);
    cudaGetSymbolAddress(&P,  g_P);    cudaGetSymbolAddress(&C,  g_C);

    static cudaStream_t s1 = nullptr, s2 = nullptr;
    static cudaEvent_t evRoot = nullptr, evWB = nullptr, evRB = nullptr, evAux = nullptr;
    static bool init_done = false;
    if (!init_done) {
        cudaFuncSetAttribute(gemm_fp16_kernel,
                             cudaFuncAttributeMaxDynamicSharedMemorySize, GEMM_SMEM);
        cudaStreamCreateWithFlags(&s1, cudaStreamNonBlocking);
        cudaStreamCreateWithFlags(&s2, cudaStreamNonBlocking);
        cudaEventCreateWithFlags(&evRoot, cudaEventDisableTiming);
        cudaEventCreateWithFlags(&evWB,   cudaEventDisableTiming);
        cudaEventCreateWithFlags(&evRB,   cudaEventDisableTiming);
        cudaEventCreateWithFlags(&evAux,  cudaEventDisableTiming);
        init_done = true;
    }

    // fork side branches off the captured legacy stream
    cudaEventRecord(evRoot, 0);
    cudaStreamWaitEvent(s1, evRoot, 0);
    cudaStreamWaitEvent(s2, evRoot, 0);

    // branch s1: R -> pack into B rows 1024..1151
    rp_r_kernel<<<dim3(64, 16), 256, 0, s1>>>(memory, Wq, (float*)R);
    pack_r_kernel<<<MSL * DIM / 4 / 256, 256, 0, s1>>>((const float*)R, (__half2*)B);
    cudaEventRecord(evRB, s1);

    // branch s2: Wf_x pack -> B rows 0..1023 (+bias); then P and c (tail deps)
    pack_wfx_kernel<<<DIM * DIM / 4 / 256, 256, 0, s2>>>(Wf, (__half2*)B, bf,
                                                         (float*)bias);
    cudaEventRecord(evWB, s2);
    rp_p_kernel<<<dim3(64, 16), 256, 0, s2>>>(memory, Wf, (float*)P);
    cvec_kernel<<<8, 256, 0, s2>>>(memory, bq, (float*)c);
    cudaEventRecord(evAux, s2);

    // main: round x -> fp16 -> GEMM (needs both B halves)
    round_x_kernel<<<NTOK * DIM / 4 / 256, 256>>>(
        (const float4*)x, (__half2*)xh, NTOK * DIM / 4);
    cudaStreamWaitEvent(0, evWB, 0);
    cudaStreamWaitEvent(0, evRB, 0);
    dim3 gg(NW / GBN, NTOK / GBM);   // (9, 128)
    gemm_fp16_kernel<<<gg, 256, GEMM_SMEM>>>(
        (const __half*)xh, (const __half*)B, (const float*)bias, (float*)C);

    // join: tail needs C, c, P
    cudaStreamWaitEvent(0, evAux, 0);
    tail_kernel<<<NTOK, 256>>>((const float*)C, (const float*)c,
                               (const float*)P, gamma, beta, out);
}